// round 1
// baseline (speedup 1.0000x reference)
#include <cuda_runtime.h>
#include <cstdint>
#include <cstddef>

// EfficientSelfAttention: B=8, N=16384 (128x128), C=64, heads=1, SR=8 -> Nr=256
// Pipeline: [wT transpose] -> [conv GEMM partials] -> [bias+LN+KV] -> [fused attention]

namespace {
constexpr int   NB     = 8;
constexpr int   NN     = 16384;
constexpr float QSCALE = 0.125f;   // 64^-0.5
}

// ---- scratch (no allocations allowed) ----
__device__ float g_wT[64 * 64 * 64];      // [k = pix*64+ic][oc], 1MB
__device__ float g_part[4 * 2048 * 64];   // conv split-k partials
__device__ float g_K[8 * 256 * 64];
__device__ float g_V[8 * 256 * 64];

using u64 = unsigned long long;

// ---- packed f32x2 helpers (FFMA2: 2 FMA per instruction on sm_103a) ----
__device__ __forceinline__ u64 pk2(float x, float y) {
    u64 r; asm("mov.b64 %0,{%1,%2};" : "=l"(r) : "f"(x), "f"(y)); return r;
}
__device__ __forceinline__ float2 upk2(u64 v) {
    float2 f; asm("mov.b64 {%0,%1},%2;" : "=f"(f.x), "=f"(f.y) : "l"(v)); return f;
}
__device__ __forceinline__ void fma2(u64 &d, u64 a, u64 b) {
    asm("fma.rn.f32x2 %0,%1,%2,%0;" : "+l"(d) : "l"(a), "l"(b));
}

// ============================================================
// Kernel 1a: transpose sr_w (oc,ic,kh,kw) -> wT[k][oc], k = pix*64+ic
// ============================================================
__global__ void k_wtrans(const float* __restrict__ srw) {
    int d   = blockIdx.x * 256 + threadIdx.x;   // 0..262143
    int oc  = d & 63;
    int k   = d >> 6;
    int ic  = k & 63;
    int pix = k >> 6;
    g_wT[d] = srw[(oc << 12) + (ic << 6) + pix];
}

// ============================================================
// Kernel 1b: conv as GEMM. A = patches (2048 x 4096), W = wT (4096 x 64).
// Tile: 32 positions x 64 oc, split-k = 4 (1024 k each, 8 chunks of 128).
// grid (64, 4), 256 threads. Writes partials to g_part[kt].
// ============================================================
__global__ void __launch_bounds__(256) k_conv(const float* __restrict__ x) {
    __shared__ float A_s[32 * 128];   // [pos][kk]
    __shared__ float W_s[128 * 64];   // [kk][oc]
    int tid = threadIdx.x;
    int pt = blockIdx.x, kt = blockIdx.y;
    int tx = tid & 15, ty = tid >> 4;

    u64 c00 = pk2(0.f, 0.f), c01 = pk2(0.f, 0.f);
    u64 c10 = pk2(0.f, 0.f), c11 = pk2(0.f, 0.f);

    for (int ck = 0; ck < 8; ck++) {
        int kb = kt * 1024 + ck * 128;
        // load W chunk (contiguous in wT)
        const float4* wsrc = (const float4*)(g_wT + kb * 64);
        float4* wd = (float4*)W_s;
#pragma unroll
        for (int j = 0; j < 8; j++) wd[tid + j * 256] = wsrc[tid + j * 256];
        // load A chunk: 32 positions x 2 pixels x 64 channels (coalesced float4)
        int pixbase = kb >> 6;
#pragma unroll
        for (int j = 0; j < 4; j++) {
            int lin  = tid + j * 256;        // 0..1023
            int c4   = lin & 15;
            int pixo = (lin >> 4) & 1;
            int i    = lin >> 5;             // 0..31
            int pos  = pt * 32 + i;
            int b    = pos >> 8, pp = pos & 255;
            int oh   = pp >> 4,  ow = pp & 15;
            int pix  = pixbase + pixo;
            int row  = oh * 8 + (pix >> 3);
            int col  = ow * 8 + (pix & 7);
            float4 v = ((const float4*)x)[(size_t)(b * 16384 + row * 128 + col) * 16 + c4];
            ((float4*)A_s)[i * 32 + pixo * 16 + c4] = v;
        }
        __syncthreads();
#pragma unroll 4
        for (int kk = 0; kk < 128; kk++) {
            float a0 = A_s[(ty * 2) * 128 + kk];
            float a1 = A_s[(ty * 2 + 1) * 128 + kk];
            u64 a0p = pk2(a0, a0), a1p = pk2(a1, a1);
            ulonglong2 wv = *(const ulonglong2*)&W_s[kk * 64 + tx * 4];
            fma2(c00, a0p, wv.x); fma2(c01, a0p, wv.y);
            fma2(c10, a1p, wv.x); fma2(c11, a1p, wv.y);
        }
        __syncthreads();
    }
    int pos0 = pt * 32 + ty * 2;
    float2 f00 = upk2(c00), f01 = upk2(c01), f10 = upk2(c10), f11 = upk2(c11);
    float4 r0 = make_float4(f00.x, f00.y, f01.x, f01.y);
    float4 r1 = make_float4(f10.x, f10.y, f11.x, f11.y);
    ((float4*)g_part)[(kt * 2048 + pos0) * 16 + tx]     = r0;
    ((float4*)g_part)[(kt * 2048 + pos0 + 1) * 16 + tx] = r1;
}

// ============================================================
// Kernel 2: sum split-k partials + conv bias -> LayerNorm -> KV projection.
// grid 32, 256 threads; each warp handles 8 rows (of 2048).
// ============================================================
__global__ void __launch_bounds__(256) k_lnkv(
    const float* __restrict__ srb, const float* __restrict__ lng,
    const float* __restrict__ lnb, const float* __restrict__ kvw,
    const float* __restrict__ kvb)
{
    __shared__ float kvw_s[128 * 68];
    __shared__ float xn_s[8 * 68];
    __shared__ float kvb_s[128], srb_s[64], lg_s[64], lb_s[64];
    int tid = threadIdx.x;
#pragma unroll
    for (int j = 0; j < 8; j++) {
        int idx4 = tid + j * 256;            // 2048 float4 = 128x64
        int r = idx4 >> 4, c4 = idx4 & 15;
        ((float4*)kvw_s)[r * 17 + c4] = ((const float4*)kvw)[idx4];
    }
    if (tid < 128) kvb_s[tid] = kvb[tid];
    if (tid >= 128 && tid < 192) {
        int c = tid - 128;
        srb_s[c] = srb[c]; lg_s[c] = lng[c]; lb_s[c] = lnb[c];
    }
    __syncthreads();

    int w = tid >> 5, lane = tid & 31;
    for (int t = 0; t < 8; t++) {
        int row = blockIdx.x * 64 + w * 8 + t;
        int c0 = lane, c1 = lane + 32;
        float v0 = srb_s[c0], v1 = srb_s[c1];
#pragma unroll
        for (int kt = 0; kt < 4; kt++) {
            v0 += g_part[kt * 131072 + row * 64 + c0];
            v1 += g_part[kt * 131072 + row * 64 + c1];
        }
        float s = v0 + v1, sq = v0 * v0 + v1 * v1;
#pragma unroll
        for (int o = 16; o; o >>= 1) {
            s  += __shfl_xor_sync(0xffffffffu, s, o);
            sq += __shfl_xor_sync(0xffffffffu, sq, o);
        }
        float mu  = s * (1.f / 64.f);
        float var = sq * (1.f / 64.f) - mu * mu;
        float inv = rsqrtf(var + 1e-5f);
        xn_s[w * 68 + c0] = (v0 - mu) * inv * lg_s[c0] + lb_s[c0];
        xn_s[w * 68 + c1] = (v1 - mu) * inv * lg_s[c1] + lb_s[c1];
        __syncwarp();
#pragma unroll
        for (int rr = 0; rr < 4; rr++) {
            int r = lane + rr * 32;
            u64 acc = pk2(0.f, 0.f);
#pragma unroll
            for (int c4 = 0; c4 < 16; c4++) {
                ulonglong2 wv = *(const ulonglong2*)&kvw_s[r * 68 + c4 * 4];
                ulonglong2 xv = *(const ulonglong2*)&xn_s[w * 68 + c4 * 4];
                fma2(acc, wv.x, xv.x); fma2(acc, wv.y, xv.y);
            }
            float2 f = upk2(acc);
            float val = f.x + f.y + kvb_s[r];
            if (r < 64) g_K[row * 64 + r] = val;
            else        g_V[row * 64 + (r - 64)] = val;
        }
        __syncwarp();
    }
}

// ============================================================
// Kernel 3: fused attention. K/V/q_w/proj_w in smem (pitch 68 -> conflict-free).
// grid (64, 8) = (query blocks of 256, batch); 512 threads, 16 queries/warp.
// ============================================================
namespace {
constexpr int SM_K    = 0;
constexpr int SM_V    = SM_K + 256 * 68;
constexpr int SM_QW   = SM_V + 256 * 68;
constexpr int SM_PW   = SM_QW + 64 * 68;
constexpr int SM_QB   = SM_PW + 64 * 68;
constexpr int SM_PB   = SM_QB + 64;
constexpr int SM_WARP = SM_PB + 64;        // 43648
constexpr int WARP_FL = 648;               // xo[68] + qv[68] + pr2[256 u64]
constexpr int ATTN_SMEM_FLOATS = SM_WARP + 16 * WARP_FL;   // 54016
constexpr int ATTN_SMEM_BYTES  = ATTN_SMEM_FLOATS * 4;     // 216064
}

__global__ void __launch_bounds__(512, 1) k_attn(
    const float* __restrict__ x,
    const float* __restrict__ qw, const float* __restrict__ qb,
    const float* __restrict__ pw, const float* __restrict__ pb,
    float* __restrict__ out)
{
    extern __shared__ float sm[];
    int tid = threadIdx.x;
    int b   = blockIdx.y;
    int nb  = blockIdx.x;

    // stage K, V (4096 float4 each), q_w, proj_w, biases
    {
        const float4* ksrc = (const float4*)g_K + b * 4096;
        const float4* vsrc = (const float4*)g_V + b * 4096;
        float4* kd = (float4*)(sm + SM_K);
        float4* vd = (float4*)(sm + SM_V);
#pragma unroll
        for (int j = 0; j < 8; j++) {
            int idx4 = tid + j * 512;
            int m = idx4 >> 4, c4 = idx4 & 15;
            kd[m * 17 + c4] = ksrc[idx4];
            vd[m * 17 + c4] = vsrc[idx4];
        }
        float4* qwd = (float4*)(sm + SM_QW);
        float4* pwd = (float4*)(sm + SM_PW);
#pragma unroll
        for (int j = 0; j < 2; j++) {
            int idx4 = tid + j * 512;
            int r = idx4 >> 4, c4 = idx4 & 15;
            qwd[r * 17 + c4] = ((const float4*)qw)[idx4];
            pwd[r * 17 + c4] = ((const float4*)pw)[idx4];
        }
        if (tid < 64) { sm[SM_QB + tid] = qb[tid]; sm[SM_PB + tid] = pb[tid]; }
    }
    __syncthreads();

    int w = tid >> 5, lane = tid & 31;
    float* xo  = sm + SM_WARP + w * WARP_FL;   // x row, later reused for o
    float* qv  = xo + 68;
    u64*   pr2 = (u64*)(xo + 136);             // softmax probs, duplicated pairs

    for (int qi = 0; qi < 16; qi++) {
        int n = nb * 256 + w * 16 + qi;
        const float* xrow = x + ((size_t)b * NN + n) * 64;
        xo[lane]      = xrow[lane];
        xo[lane + 32] = xrow[lane + 32];
        __syncwarp();

        // ---- q projection (scale folded in) ----
        {
            int j0 = lane, j1 = lane + 32;
            u64 a0 = pk2(0.f, 0.f), a1 = pk2(0.f, 0.f);
#pragma unroll
            for (int c4 = 0; c4 < 16; c4++) {
                ulonglong2 xv = *(const ulonglong2*)&xo[c4 * 4];
                ulonglong2 w0 = *(const ulonglong2*)&sm[SM_QW + j0 * 68 + c4 * 4];
                ulonglong2 w1 = *(const ulonglong2*)&sm[SM_QW + j1 * 68 + c4 * 4];
                fma2(a0, w0.x, xv.x); fma2(a0, w0.y, xv.y);
                fma2(a1, w1.x, xv.x); fma2(a1, w1.y, xv.y);
            }
            float2 f0 = upk2(a0), f1 = upk2(a1);
            qv[j0] = (f0.x + f0.y + sm[SM_QB + j0]) * QSCALE;
            qv[j1] = (f1.x + f1.y + sm[SM_QB + j1]) * QSCALE;
        }
        __syncwarp();

        // ---- scores: lane owns keys m = 32r + lane ----
        u64 accs[8];
#pragma unroll
        for (int r = 0; r < 8; r++) accs[r] = pk2(0.f, 0.f);
#pragma unroll
        for (int c4 = 0; c4 < 16; c4++) {
            ulonglong2 q2 = *(const ulonglong2*)&qv[c4 * 4];
#pragma unroll
            for (int r = 0; r < 8; r++) {
                int m = r * 32 + lane;
                ulonglong2 k2 = *(const ulonglong2*)&sm[SM_K + m * 68 + c4 * 4];
                fma2(accs[r], k2.x, q2.x); fma2(accs[r], k2.y, q2.y);
            }
        }
        // ---- softmax over 256 ----
        float sc[8];
        float mx = -1e30f;
#pragma unroll
        for (int r = 0; r < 8; r++) {
            float2 f = upk2(accs[r]);
            sc[r] = f.x + f.y;
            mx = fmaxf(mx, sc[r]);
        }
#pragma unroll
        for (int o = 16; o; o >>= 1) mx = fmaxf(mx, __shfl_xor_sync(0xffffffffu, mx, o));
        float sum = 0.f;
#pragma unroll
        for (int r = 0; r < 8; r++) { sc[r] = __expf(sc[r] - mx); sum += sc[r]; }
#pragma unroll
        for (int o = 16; o; o >>= 1) sum += __shfl_xor_sync(0xffffffffu, sum, o);
        float inv = 1.f / sum;
#pragma unroll
        for (int r = 0; r < 8; r++) {
            float p = sc[r] * inv;
            pr2[r * 32 + lane] = pk2(p, p);
        }
        __syncwarp();

        // ---- P @ V: lane owns output pair (2*lane, 2*lane+1) ----
        u64 oacc = pk2(0.f, 0.f);
        int joff = 2 * lane;
#pragma unroll 4
        for (int m = 0; m < 256; m += 2) {
            ulonglong2 p2 = *(const ulonglong2*)&pr2[m];
            u64 v0 = *(const u64*)&sm[SM_V + m * 68 + joff];
            u64 v1 = *(const u64*)&sm[SM_V + (m + 1) * 68 + joff];
            fma2(oacc, p2.x, v0);
            fma2(oacc, p2.y, v1);
        }
        {
            float2 f = upk2(oacc);
            xo[joff]     = f.x;   // xo reuse: safe, last read was before a __syncwarp
            xo[joff + 1] = f.y;
        }
        __syncwarp();

        // ---- output projection + bias -> global ----
        {
            int j0 = lane, j1 = lane + 32;
            u64 a0 = pk2(0.f, 0.f), a1 = pk2(0.f, 0.f);
#pragma unroll
            for (int c4 = 0; c4 < 16; c4++) {
                ulonglong2 xv = *(const ulonglong2*)&xo[c4 * 4];
                ulonglong2 w0 = *(const ulonglong2*)&sm[SM_PW + j0 * 68 + c4 * 4];
                ulonglong2 w1 = *(const ulonglong2*)&sm[SM_PW + j1 * 68 + c4 * 4];
                fma2(a0, w0.x, xv.x); fma2(a0, w0.y, xv.y);
                fma2(a1, w1.x, xv.x); fma2(a1, w1.y, xv.y);
            }
            float2 f0 = upk2(a0), f1 = upk2(a1);
            float* orow = out + ((size_t)b * NN + n) * 64;
            orow[j0] = f0.x + f0.y + sm[SM_PB + j0];
            orow[j1] = f1.x + f1.y + sm[SM_PB + j1];
        }
        __syncwarp();
    }
}

// ============================================================
extern "C" void kernel_launch(void* const* d_in, const int* in_sizes, int n_in,
                              void* d_out, int out_size) {
    const float* x   = (const float*)d_in[0];
    const float* srw = (const float*)d_in[1];
    const float* srb = (const float*)d_in[2];
    const float* lng = (const float*)d_in[3];
    const float* lnb = (const float*)d_in[4];
    const float* qw  = (const float*)d_in[5];
    const float* qb  = (const float*)d_in[6];
    const float* kvw = (const float*)d_in[7];
    const float* kvb = (const float*)d_in[8];
    const float* pw  = (const float*)d_in[9];
    const float* pb  = (const float*)d_in[10];
    float* out = (float*)d_out;

    k_wtrans<<<1024, 256>>>(srw);
    k_conv<<<dim3(64, 4), 256>>>(x);
    k_lnkv<<<32, 256>>>(srb, lng, lnb, kvw, kvb);
    cudaFuncSetAttribute(k_attn, cudaFuncAttributeMaxDynamicSharedMemorySize, ATTN_SMEM_BYTES);
    k_attn<<<dim3(64, 8), 512, ATTN_SMEM_BYTES>>>(x, qw, qb, pw, pb, out);
}

// round 2
// speedup vs baseline: 2.4478x; 2.4478x over previous
#include <cuda_runtime.h>
#include <cstdint>
#include <cstddef>

// EfficientSelfAttention: B=8, N=16384 (128x128), C=64, heads=1, SR=8 -> Nr=256
// R2: fold q-proj into K (K2T, kb2) and out-proj into V (V2); register-blocked
// outer-product attention GEMMs (8q x 8m per lane, packed f32x2 FMA).

namespace {
constexpr int   NB     = 8;
constexpr int   NN     = 16384;
constexpr float QSCALE = 0.125f;   // 64^-0.5
}

// ---- scratch ----
__device__ float g_wT[64 * 64 * 64];
__device__ float g_part[4 * 2048 * 64];
__device__ float g_K[8 * 256 * 64];
__device__ float g_V[8 * 256 * 64];
__device__ float g_K2T[8 * 64 * 256];   // [b][i][m] = scale * sum_o qw[o][i] K[m][o]
__device__ float g_V2[8 * 256 * 64];    // [b][m][c] = sum_j V[m][j] pw[c][j]
__device__ float g_kb2[8 * 256];        // [b][m]    = scale * sum_o qb[o] K[m][o]

using u64 = unsigned long long;

__device__ __forceinline__ u64 pk2(float x, float y) {
    u64 r; asm("mov.b64 %0,{%1,%2};" : "=l"(r) : "f"(x), "f"(y)); return r;
}
__device__ __forceinline__ float2 upk2(u64 v) {
    float2 f; asm("mov.b64 {%0,%1},%2;" : "=f"(f.x), "=f"(f.y) : "l"(v)); return f;
}
__device__ __forceinline__ void fma2(u64 &d, u64 a, u64 b) {
    asm("fma.rn.f32x2 %0,%1,%2,%0;" : "+l"(d) : "l"(a), "l"(b));
}

// ============================================================
// Kernel 1a: transpose sr_w -> wT[k][oc]
// ============================================================
__global__ void k_wtrans(const float* __restrict__ srw) {
    int d   = blockIdx.x * 256 + threadIdx.x;
    int oc  = d & 63;
    int k   = d >> 6;
    int ic  = k & 63;
    int pix = k >> 6;
    g_wT[d] = srw[(oc << 12) + (ic << 6) + pix];
}

// ============================================================
// Kernel 1b: conv as GEMM (unchanged from R1 — passed)
// ============================================================
__global__ void __launch_bounds__(256) k_conv(const float* __restrict__ x) {
    __shared__ float A_s[32 * 128];
    __shared__ float W_s[128 * 64];
    int tid = threadIdx.x;
    int pt = blockIdx.x, kt = blockIdx.y;
    int tx = tid & 15, ty = tid >> 4;

    u64 c00 = pk2(0.f, 0.f), c01 = pk2(0.f, 0.f);
    u64 c10 = pk2(0.f, 0.f), c11 = pk2(0.f, 0.f);

    for (int ck = 0; ck < 8; ck++) {
        int kb = kt * 1024 + ck * 128;
        const float4* wsrc = (const float4*)(g_wT + kb * 64);
        float4* wd = (float4*)W_s;
#pragma unroll
        for (int j = 0; j < 8; j++) wd[tid + j * 256] = wsrc[tid + j * 256];
        int pixbase = kb >> 6;
#pragma unroll
        for (int j = 0; j < 4; j++) {
            int lin  = tid + j * 256;
            int c4   = lin & 15;
            int pixo = (lin >> 4) & 1;
            int i    = lin >> 5;
            int pos  = pt * 32 + i;
            int b    = pos >> 8, pp = pos & 255;
            int oh   = pp >> 4,  ow = pp & 15;
            int pix  = pixbase + pixo;
            int row  = oh * 8 + (pix >> 3);
            int col  = ow * 8 + (pix & 7);
            float4 v = ((const float4*)x)[(size_t)(b * 16384 + row * 128 + col) * 16 + c4];
            ((float4*)A_s)[i * 32 + pixo * 16 + c4] = v;
        }
        __syncthreads();
#pragma unroll 4
        for (int kk = 0; kk < 128; kk++) {
            float a0 = A_s[(ty * 2) * 128 + kk];
            float a1 = A_s[(ty * 2 + 1) * 128 + kk];
            u64 a0p = pk2(a0, a0), a1p = pk2(a1, a1);
            ulonglong2 wv = *(const ulonglong2*)&W_s[kk * 64 + tx * 4];
            fma2(c00, a0p, wv.x); fma2(c01, a0p, wv.y);
            fma2(c10, a1p, wv.x); fma2(c11, a1p, wv.y);
        }
        __syncthreads();
    }
    int pos0 = pt * 32 + ty * 2;
    float2 f00 = upk2(c00), f01 = upk2(c01), f10 = upk2(c10), f11 = upk2(c11);
    float4 r0 = make_float4(f00.x, f00.y, f01.x, f01.y);
    float4 r1 = make_float4(f10.x, f10.y, f11.x, f11.y);
    ((float4*)g_part)[(kt * 2048 + pos0) * 16 + tx]     = r0;
    ((float4*)g_part)[(kt * 2048 + pos0 + 1) * 16 + tx] = r1;
}

// ============================================================
// Kernel 2: partial sum + bias -> LayerNorm -> KV projection (unchanged)
// ============================================================
__global__ void __launch_bounds__(256) k_lnkv(
    const float* __restrict__ srb, const float* __restrict__ lng,
    const float* __restrict__ lnb, const float* __restrict__ kvw,
    const float* __restrict__ kvb)
{
    __shared__ float kvw_s[128 * 68];
    __shared__ float xn_s[8 * 68];
    __shared__ float kvb_s[128], srb_s[64], lg_s[64], lb_s[64];
    int tid = threadIdx.x;
#pragma unroll
    for (int j = 0; j < 8; j++) {
        int idx4 = tid + j * 256;
        int r = idx4 >> 4, c4 = idx4 & 15;
        ((float4*)kvw_s)[r * 17 + c4] = ((const float4*)kvw)[idx4];
    }
    if (tid < 128) kvb_s[tid] = kvb[tid];
    if (tid >= 128 && tid < 192) {
        int c = tid - 128;
        srb_s[c] = srb[c]; lg_s[c] = lng[c]; lb_s[c] = lnb[c];
    }
    __syncthreads();

    int w = tid >> 5, lane = tid & 31;
    for (int t = 0; t < 8; t++) {
        int row = blockIdx.x * 64 + w * 8 + t;
        int c0 = lane, c1 = lane + 32;
        float v0 = srb_s[c0], v1 = srb_s[c1];
#pragma unroll
        for (int kt = 0; kt < 4; kt++) {
            v0 += g_part[kt * 131072 + row * 64 + c0];
            v1 += g_part[kt * 131072 + row * 64 + c1];
        }
        float s = v0 + v1, sq = v0 * v0 + v1 * v1;
#pragma unroll
        for (int o = 16; o; o >>= 1) {
            s  += __shfl_xor_sync(0xffffffffu, s, o);
            sq += __shfl_xor_sync(0xffffffffu, sq, o);
        }
        float mu  = s * (1.f / 64.f);
        float var = sq * (1.f / 64.f) - mu * mu;
        float inv = rsqrtf(var + 1e-5f);
        xn_s[w * 68 + c0] = (v0 - mu) * inv * lg_s[c0] + lb_s[c0];
        xn_s[w * 68 + c1] = (v1 - mu) * inv * lg_s[c1] + lb_s[c1];
        __syncwarp();
#pragma unroll
        for (int rr = 0; rr < 4; rr++) {
            int r = lane + rr * 32;
            u64 acc = pk2(0.f, 0.f);
#pragma unroll
            for (int c4 = 0; c4 < 16; c4++) {
                ulonglong2 wv = *(const ulonglong2*)&kvw_s[r * 68 + c4 * 4];
                ulonglong2 xv = *(const ulonglong2*)&xn_s[w * 68 + c4 * 4];
                fma2(acc, wv.x, xv.x); fma2(acc, wv.y, xv.y);
            }
            float2 f = upk2(acc);
            float val = f.x + f.y + kvb_s[r];
            if (r < 64) g_K[row * 64 + r] = val;
            else        g_V[row * 64 + (r - 64)] = val;
        }
        __syncwarp();
    }
}

// ============================================================
// Kernel 2b: fold projections.
//   K2T[b][i][m] = scale * sum_o qw[o][i]*K[b][m][o]
//   kb2[b][m]    = scale * sum_o qb[o]   *K[b][m][o]
//   V2 [b][m][c] = sum_j V[b][m][j]*pw[c][j]
// grid 8 (batch), 256 threads (thread = key m).
// ============================================================
__global__ void __launch_bounds__(256) k_fold(
    const float* __restrict__ qw, const float* __restrict__ qb,
    const float* __restrict__ pw)
{
    __shared__ float qwT_s[64 * 68];
    __shared__ float pw_s[64 * 68];
    __shared__ float qb_s[64];
    int tid = threadIdx.x;
    int b = blockIdx.x;
#pragma unroll
    for (int j = 0; j < 4; j++) {
        int idx4 = tid + j * 256;           // 1024 float4 = 64x64
        int r = idx4 >> 4, c4 = idx4 & 15;
        float4 v = ((const float4*)qw)[idx4];
        qwT_s[(c4 * 4 + 0) * 68 + r] = v.x;
        qwT_s[(c4 * 4 + 1) * 68 + r] = v.y;
        qwT_s[(c4 * 4 + 2) * 68 + r] = v.z;
        qwT_s[(c4 * 4 + 3) * 68 + r] = v.w;
        ((float4*)pw_s)[r * 17 + c4] = ((const float4*)pw)[idx4];
    }
    if (tid < 64) qb_s[tid] = qb[tid];
    __syncthreads();

    int m = tid;
    // K row in registers (as pairs)
    u64 kr[32];
    {
        const ulonglong2* src = (const ulonglong2*)(g_K + (b * 256 + m) * 64);
#pragma unroll
        for (int j = 0; j < 16; j++) { ulonglong2 v = src[j]; kr[2*j] = v.x; kr[2*j+1] = v.y; }
    }
    // kb2
    {
        u64 acc = pk2(0.f, 0.f);
        const ulonglong2* qbp = (const ulonglong2*)qb_s;
#pragma unroll
        for (int j = 0; j < 16; j++) { ulonglong2 v = qbp[j]; fma2(acc, kr[2*j], v.x); fma2(acc, kr[2*j+1], v.y); }
        float2 f = upk2(acc);
        g_kb2[b * 256 + m] = QSCALE * (f.x + f.y);
    }
    // K2T rows
    for (int i = 0; i < 64; i++) {
        u64 acc = pk2(0.f, 0.f);
        const ulonglong2* qp = (const ulonglong2*)&qwT_s[i * 68];
#pragma unroll
        for (int j = 0; j < 16; j++) { ulonglong2 v = qp[j]; fma2(acc, kr[2*j], v.x); fma2(acc, kr[2*j+1], v.y); }
        float2 f = upk2(acc);
        g_K2T[(b * 64 + i) * 256 + m] = QSCALE * (f.x + f.y);
    }
    // V row -> V2
    u64 vr[32];
    {
        const ulonglong2* src = (const ulonglong2*)(g_V + (b * 256 + m) * 64);
#pragma unroll
        for (int j = 0; j < 16; j++) { ulonglong2 v = src[j]; vr[2*j] = v.x; vr[2*j+1] = v.y; }
    }
    for (int c = 0; c < 64; c++) {
        u64 acc = pk2(0.f, 0.f);
        const ulonglong2* pp = (const ulonglong2*)&pw_s[c * 68];
#pragma unroll
        for (int j = 0; j < 16; j++) { ulonglong2 v = pp[j]; fma2(acc, vr[2*j], v.x); fma2(acc, vr[2*j+1], v.y); }
        float2 f = upk2(acc);
        g_V2[(b * 256 + m) * 64 + c] = f.x + f.y;
    }
}

// ============================================================
// Kernel 3: blocked attention. CTA = 64 queries, 256 threads (8 warps).
//   scores S[64][256] = xT-blocked outer-product GEMM vs K2T
//   softmax (+kb2) -> P_T[256][64]
//   O[64][64] = P @ V2 via outer product, 4-way m-split + reduce
// ============================================================
namespace {
constexpr int OFF_XT  = 0;                       // x_T[64][68]
constexpr int OFF_A   = OFF_XT + 64 * 68;        // K2T_s[64][260]  /  P_T[256][68]
constexpr int OFF_V2  = OFF_A + 17408;           // V2_s[256][68]
constexpr int OFF_S   = OFF_V2 + 17408;          // S_s[64][260]    /  Opart[4][64][64]
constexpr int OFF_KB  = OFF_S + 16640;           // kb2[256]
constexpr int OFF_PB  = OFF_KB + 256;            // pb[64]
constexpr int ATTN_FLOATS = OFF_PB + 64;         // 56128
constexpr int ATTN_BYTES  = ATTN_FLOATS * 4;     // 224512
}

__global__ void __launch_bounds__(256, 1) k_attn2(
    const float* __restrict__ x, const float* __restrict__ pb,
    float* __restrict__ out)
{
    extern __shared__ float sm[];
    int tid = threadIdx.x;
    int b   = blockIdx.y;
    int q0  = blockIdx.x * 64;

    // ---- stage ----
#pragma unroll
    for (int j = 0; j < 4; j++) {                 // x block, transposed
        int idx4 = tid + j * 256;                 // 1024 float4
        int r = idx4 >> 4, c4 = idx4 & 15;
        float4 v = ((const float4*)x)[(size_t)(b * NN + q0 + r) * 16 + c4];
        int cb = c4 * 4;
        sm[OFF_XT + (cb + 0) * 68 + r] = v.x;
        sm[OFF_XT + (cb + 1) * 68 + r] = v.y;
        sm[OFF_XT + (cb + 2) * 68 + r] = v.z;
        sm[OFF_XT + (cb + 3) * 68 + r] = v.w;
    }
#pragma unroll
    for (int j = 0; j < 16; j++) {                // K2T: [64][256] -> pitch 260
        int idx4 = tid + j * 256;                 // 4096 float4
        int i = idx4 >> 6, m4 = idx4 & 63;
        *(float4*)&sm[OFF_A + i * 260 + m4 * 4] =
            ((const float4*)g_K2T)[(b * 64 + i) * 64 + m4];
    }
#pragma unroll
    for (int j = 0; j < 16; j++) {                // V2: [256][64] -> pitch 68
        int idx4 = tid + j * 256;
        int m = idx4 >> 4, c4 = idx4 & 15;
        *(float4*)&sm[OFF_V2 + m * 68 + c4 * 4] =
            ((const float4*)g_V2)[(b * 256 + m) * 16 + c4];
    }
    sm[OFF_KB + tid] = g_kb2[b * 256 + tid];
    if (tid < 64) sm[OFF_PB + tid] = pb[tid];
    __syncthreads();

    int w = tid >> 5, lane = tid & 31;

    // ---- scores: warp (wq in [0,4), wm in [0,2)), lane 8q x 8m ----
    {
        int wq = w >> 1, wm = w & 1;
        int qg = lane >> 4, mg = lane & 15;
        int qbase = wq * 16 + qg * 8;
        int mbase = wm * 128 + mg * 8;
        u64 c2[8][4];
#pragma unroll
        for (int q = 0; q < 8; q++)
#pragma unroll
            for (int p = 0; p < 4; p++) c2[q][p] = pk2(0.f, 0.f);

#pragma unroll 4
        for (int i = 0; i < 64; i++) {
            float4 a0 = *(const float4*)&sm[OFF_XT + i * 68 + qbase];
            float4 a1 = *(const float4*)&sm[OFF_XT + i * 68 + qbase + 4];
            ulonglong2 B0 = *(const ulonglong2*)&sm[OFF_A + i * 260 + mbase];
            ulonglong2 B1 = *(const ulonglong2*)&sm[OFF_A + i * 260 + mbase + 4];
            float aq[8] = {a0.x, a0.y, a0.z, a0.w, a1.x, a1.y, a1.z, a1.w};
#pragma unroll
            for (int q = 0; q < 8; q++) {
                u64 ad = pk2(aq[q], aq[q]);
                fma2(c2[q][0], ad, B0.x); fma2(c2[q][1], ad, B0.y);
                fma2(c2[q][2], ad, B1.x); fma2(c2[q][3], ad, B1.y);
            }
        }
#pragma unroll
        for (int q = 0; q < 8; q++) {
            float2 f0 = upk2(c2[q][0]), f1 = upk2(c2[q][1]);
            float2 f2 = upk2(c2[q][2]), f3 = upk2(c2[q][3]);
            int qrow = qbase + q;
            *(float4*)&sm[OFF_S + qrow * 260 + mbase]     = make_float4(f0.x, f0.y, f1.x, f1.y);
            *(float4*)&sm[OFF_S + qrow * 260 + mbase + 4] = make_float4(f2.x, f2.y, f3.x, f3.y);
        }
    }
    __syncthreads();

    // ---- softmax (+kb2) -> P_T[256][68] over region A ----
    {
        float kb[8];
#pragma unroll
        for (int j = 0; j < 8; j++) kb[j] = sm[OFF_KB + lane + 32 * j];
        for (int t = 0; t < 8; t++) {
            int q = w * 8 + t;
            float s[8];
#pragma unroll
            for (int j = 0; j < 8; j++) s[j] = sm[OFF_S + q * 260 + lane + 32 * j] + kb[j];
            float mx = s[0];
#pragma unroll
            for (int j = 1; j < 8; j++) mx = fmaxf(mx, s[j]);
#pragma unroll
            for (int o = 16; o; o >>= 1) mx = fmaxf(mx, __shfl_xor_sync(0xffffffffu, mx, o));
            float sum = 0.f;
#pragma unroll
            for (int j = 0; j < 8; j++) { s[j] = __expf(s[j] - mx); sum += s[j]; }
#pragma unroll
            for (int o = 16; o; o >>= 1) sum += __shfl_xor_sync(0xffffffffu, sum, o);
            float inv = 1.f / sum;
#pragma unroll
            for (int j = 0; j < 8; j++)
                sm[OFF_A + (lane + 32 * j) * 68 + q] = s[j] * inv;
        }
    }
    __syncthreads();

    // ---- PV: warp (wq in [0,2), wm in [0,4)), lane 8q x 8c, partial over 64 m ----
    {
        int wq = w >> 2, wm = w & 3;
        int qg = lane >> 3, cg = lane & 7;
        int qbase = wq * 32 + qg * 8;
        int cbase = cg * 8;
        u64 o2[8][4];
#pragma unroll
        for (int q = 0; q < 8; q++)
#pragma unroll
            for (int p = 0; p < 4; p++) o2[q][p] = pk2(0.f, 0.f);

        int m0 = wm * 64;
#pragma unroll 4
        for (int mi = 0; mi < 64; mi++) {
            int m = m0 + mi;
            float4 a0 = *(const float4*)&sm[OFF_A + m * 68 + qbase];
            float4 a1 = *(const float4*)&sm[OFF_A + m * 68 + qbase + 4];
            ulonglong2 B0 = *(const ulonglong2*)&sm[OFF_V2 + m * 68 + cbase];
            ulonglong2 B1 = *(const ulonglong2*)&sm[OFF_V2 + m * 68 + cbase + 4];
            float aq[8] = {a0.x, a0.y, a0.z, a0.w, a1.x, a1.y, a1.z, a1.w};
#pragma unroll
            for (int q = 0; q < 8; q++) {
                u64 ad = pk2(aq[q], aq[q]);
                fma2(o2[q][0], ad, B0.x); fma2(o2[q][1], ad, B0.y);
                fma2(o2[q][2], ad, B1.x); fma2(o2[q][3], ad, B1.y);
            }
        }
        // write partials into S region: Opart[wm][64][64]
#pragma unroll
        for (int q = 0; q < 8; q++) {
            float2 f0 = upk2(o2[q][0]), f1 = upk2(o2[q][1]);
            float2 f2 = upk2(o2[q][2]), f3 = upk2(o2[q][3]);
            int qrow = qbase + q;
            *(float4*)&sm[OFF_S + (wm * 64 + qrow) * 64 + cbase]     = make_float4(f0.x, f0.y, f1.x, f1.y);
            *(float4*)&sm[OFF_S + (wm * 64 + qrow) * 64 + cbase + 4] = make_float4(f2.x, f2.y, f3.x, f3.y);
        }
    }
    __syncthreads();

    // ---- reduce 4 partials + pb -> out ----
#pragma unroll
    for (int j = 0; j < 4; j++) {
        int idx4 = tid + j * 256;                 // 1024 float4 = 64x64
        int q = idx4 >> 4, c4 = idx4 & 15;
        float4 r = *(const float4*)&sm[OFF_S + (q * 64 + c4 * 4)];
#pragma unroll
        for (int p = 1; p < 4; p++) {
            float4 t = *(const float4*)&sm[OFF_S + ((p * 64 + q) * 64 + c4 * 4)];
            r.x += t.x; r.y += t.y; r.z += t.z; r.w += t.w;
        }
        float4 pbv = *(const float4*)&sm[OFF_PB + c4 * 4];
        r.x += pbv.x; r.y += pbv.y; r.z += pbv.z; r.w += pbv.w;
        ((float4*)out)[(size_t)(b * NN + q0 + q) * 16 + c4] = r;
    }
}

// ============================================================
extern "C" void kernel_launch(void* const* d_in, const int* in_sizes, int n_in,
                              void* d_out, int out_size) {
    const float* x   = (const float*)d_in[0];
    const float* srw = (const float*)d_in[1];
    const float* srb = (const float*)d_in[2];
    const float* lng = (const float*)d_in[3];
    const float* lnb = (const float*)d_in[4];
    const float* qw  = (const float*)d_in[5];
    const float* qb  = (const float*)d_in[6];
    const float* kvw = (const float*)d_in[7];
    const float* kvb = (const float*)d_in[8];
    const float* pw  = (const float*)d_in[9];
    const float* pb  = (const float*)d_in[10];
    float* out = (float*)d_out;

    k_wtrans<<<1024, 256>>>(srw);
    k_conv<<<dim3(64, 4), 256>>>(x);
    k_lnkv<<<32, 256>>>(srb, lng, lnb, kvw, kvb);
    k_fold<<<8, 256>>>(qw, qb, pw);
    cudaFuncSetAttribute(k_attn2, cudaFuncAttributeMaxDynamicSharedMemorySize, ATTN_BYTES);
    k_attn2<<<dim3(256, 8), 256, ATTN_BYTES>>>(x, pb, out);
}

// round 4
// speedup vs baseline: 4.8029x; 1.9621x over previous
#include <cuda_runtime.h>
#include <cstdint>
#include <cstddef>

// EfficientSelfAttention: B=8, N=16384 (128x128), C=64, heads=1, SR=8 -> Nr=256
// R4: attention GEMMs via mma.sync.m16n8k8.tf32 (base-ISA HMMA; tcgen05 needs
// sm_103a target which this toolchain does not emit). E-1 trick keeps tf32 safe:
// out = (colsum(V2) + (exp(S+kb)-1) @ V2) / (256 + rowsum) + pb.

namespace {
constexpr int   NB     = 8;
constexpr int   NN     = 16384;
constexpr float QSCALE = 0.125f;   // 64^-0.5
}

// ---- scratch ----
__device__ float g_wT[64 * 64 * 64];
__device__ float g_part[4 * 2048 * 64];
__device__ float g_K[8 * 256 * 64];
__device__ float g_V[8 * 256 * 64];
__device__ float g_K2T[8 * 64 * 256];   // [b][i][m] = scale * sum_o qw[o][i] K[m][o]
__device__ float g_V2[8 * 256 * 64];    // [b][m][c] = sum_j V[m][j] pw[c][j]
__device__ float g_kb2[8 * 256];        // [b][m]
__device__ float g_colsum[8 * 64];      // [b][c] = sum_m V2[m][c]

using u64 = unsigned long long;
using u32 = unsigned int;

__device__ __forceinline__ u64 pk2(float x, float y) {
    u64 r; asm("mov.b64 %0,{%1,%2};" : "=l"(r) : "f"(x), "f"(y)); return r;
}
__device__ __forceinline__ float2 upk2(u64 v) {
    float2 f; asm("mov.b64 {%0,%1},%2;" : "=f"(f.x), "=f"(f.y) : "l"(v)); return f;
}
__device__ __forceinline__ void fma2(u64 &d, u64 a, u64 b) {
    asm("fma.rn.f32x2 %0,%1,%2,%0;" : "+l"(d) : "l"(a), "l"(b));
}
// tf32 mma: D(16x8) += A(16x8) * B(8x8); raw fp32 bits as tf32 operands.
__device__ __forceinline__ void mma1688(float* d, u32 a0, u32 a1, u32 a2, u32 a3,
                                        u32 b0, u32 b1) {
    asm volatile(
        "mma.sync.aligned.m16n8k8.row.col.f32.tf32.tf32.f32 "
        "{%0,%1,%2,%3}, {%4,%5,%6,%7}, {%8,%9}, {%0,%1,%2,%3};"
        : "+f"(d[0]), "+f"(d[1]), "+f"(d[2]), "+f"(d[3])
        : "r"(a0), "r"(a1), "r"(a2), "r"(a3), "r"(b0), "r"(b1));
}

// ============================================================
// Kernel 1a: transpose sr_w -> wT[k][oc]
// ============================================================
__global__ void k_wtrans(const float* __restrict__ srw) {
    int d   = blockIdx.x * 256 + threadIdx.x;
    int oc  = d & 63;
    int k   = d >> 6;
    int ic  = k & 63;
    int pix = k >> 6;
    g_wT[d] = srw[(oc << 12) + (ic << 6) + pix];
}

// ============================================================
// Kernel 1b: conv as GEMM (unchanged — known good)
// ============================================================
__global__ void __launch_bounds__(256) k_conv(const float* __restrict__ x) {
    __shared__ float A_s[32 * 128];
    __shared__ float W_s[128 * 64];
    int tid = threadIdx.x;
    int pt = blockIdx.x, kt = blockIdx.y;
    int tx = tid & 15, ty = tid >> 4;

    u64 c00 = pk2(0.f, 0.f), c01 = pk2(0.f, 0.f);
    u64 c10 = pk2(0.f, 0.f), c11 = pk2(0.f, 0.f);

    for (int ck = 0; ck < 8; ck++) {
        int kb = kt * 1024 + ck * 128;
        const float4* wsrc = (const float4*)(g_wT + kb * 64);
        float4* wd = (float4*)W_s;
#pragma unroll
        for (int j = 0; j < 8; j++) wd[tid + j * 256] = wsrc[tid + j * 256];
        int pixbase = kb >> 6;
#pragma unroll
        for (int j = 0; j < 4; j++) {
            int lin  = tid + j * 256;
            int c4   = lin & 15;
            int pixo = (lin >> 4) & 1;
            int i    = lin >> 5;
            int pos  = pt * 32 + i;
            int b    = pos >> 8, pp = pos & 255;
            int oh   = pp >> 4,  ow = pp & 15;
            int pix  = pixbase + pixo;
            int row  = oh * 8 + (pix >> 3);
            int col  = ow * 8 + (pix & 7);
            float4 v = ((const float4*)x)[(size_t)(b * 16384 + row * 128 + col) * 16 + c4];
            ((float4*)A_s)[i * 32 + pixo * 16 + c4] = v;
        }
        __syncthreads();
#pragma unroll 4
        for (int kk = 0; kk < 128; kk++) {
            float a0 = A_s[(ty * 2) * 128 + kk];
            float a1 = A_s[(ty * 2 + 1) * 128 + kk];
            u64 a0p = pk2(a0, a0), a1p = pk2(a1, a1);
            ulonglong2 wv = *(const ulonglong2*)&W_s[kk * 64 + tx * 4];
            fma2(c00, a0p, wv.x); fma2(c01, a0p, wv.y);
            fma2(c10, a1p, wv.x); fma2(c11, a1p, wv.y);
        }
        __syncthreads();
    }
    int pos0 = pt * 32 + ty * 2;
    float2 f00 = upk2(c00), f01 = upk2(c01), f10 = upk2(c10), f11 = upk2(c11);
    float4 r0 = make_float4(f00.x, f00.y, f01.x, f01.y);
    float4 r1 = make_float4(f10.x, f10.y, f11.x, f11.y);
    ((float4*)g_part)[(kt * 2048 + pos0) * 16 + tx]     = r0;
    ((float4*)g_part)[(kt * 2048 + pos0 + 1) * 16 + tx] = r1;
}

// ============================================================
// Kernel 2: partial sum + bias -> LayerNorm -> KV projection (unchanged)
// ============================================================
__global__ void __launch_bounds__(256) k_lnkv(
    const float* __restrict__ srb, const float* __restrict__ lng,
    const float* __restrict__ lnb, const float* __restrict__ kvw,
    const float* __restrict__ kvb)
{
    __shared__ float kvw_s[128 * 68];
    __shared__ float xn_s[8 * 68];
    __shared__ float kvb_s[128], srb_s[64], lg_s[64], lb_s[64];
    int tid = threadIdx.x;
#pragma unroll
    for (int j = 0; j < 8; j++) {
        int idx4 = tid + j * 256;
        int r = idx4 >> 4, c4 = idx4 & 15;
        ((float4*)kvw_s)[r * 17 + c4] = ((const float4*)kvw)[idx4];
    }
    if (tid < 128) kvb_s[tid] = kvb[tid];
    if (tid >= 128 && tid < 192) {
        int c = tid - 128;
        srb_s[c] = srb[c]; lg_s[c] = lng[c]; lb_s[c] = lnb[c];
    }
    __syncthreads();

    int w = tid >> 5, lane = tid & 31;
    for (int t = 0; t < 8; t++) {
        int row = blockIdx.x * 64 + w * 8 + t;
        int c0 = lane, c1 = lane + 32;
        float v0 = srb_s[c0], v1 = srb_s[c1];
#pragma unroll
        for (int kt = 0; kt < 4; kt++) {
            v0 += g_part[kt * 131072 + row * 64 + c0];
            v1 += g_part[kt * 131072 + row * 64 + c1];
        }
        float s = v0 + v1, sq = v0 * v0 + v1 * v1;
#pragma unroll
        for (int o = 16; o; o >>= 1) {
            s  += __shfl_xor_sync(0xffffffffu, s, o);
            sq += __shfl_xor_sync(0xffffffffu, sq, o);
        }
        float mu  = s * (1.f / 64.f);
        float var = sq * (1.f / 64.f) - mu * mu;
        float inv = rsqrtf(var + 1e-5f);
        xn_s[w * 68 + c0] = (v0 - mu) * inv * lg_s[c0] + lb_s[c0];
        xn_s[w * 68 + c1] = (v1 - mu) * inv * lg_s[c1] + lb_s[c1];
        __syncwarp();
#pragma unroll
        for (int rr = 0; rr < 4; rr++) {
            int r = lane + rr * 32;
            u64 acc = pk2(0.f, 0.f);
#pragma unroll
            for (int c4 = 0; c4 < 16; c4++) {
                ulonglong2 wv = *(const ulonglong2*)&kvw_s[r * 68 + c4 * 4];
                ulonglong2 xv = *(const ulonglong2*)&xn_s[w * 68 + c4 * 4];
                fma2(acc, wv.x, xv.x); fma2(acc, wv.y, xv.y);
            }
            float2 f = upk2(acc);
            float val = f.x + f.y + kvb_s[r];
            if (r < 64) g_K[row * 64 + r] = val;
            else        g_V[row * 64 + (r - 64)] = val;
        }
        __syncwarp();
    }
}

// ============================================================
// Kernel 2b: fold projections. grid (8 batch, 4 part), 256 threads (thread = m).
//  parts 0,1: V2 c[0:32)/[32:64) + colsum;  parts 2,3: K2T i[0:32)/[32:64) (+kb2 on 2)
// ============================================================
__global__ void __launch_bounds__(256) k_fold(
    const float* __restrict__ qw, const float* __restrict__ qb,
    const float* __restrict__ pw)
{
    __shared__ float wmat[64 * 68];
    __shared__ float red[32 * 257];
    __shared__ float qb_s[64];
    int tid = threadIdx.x;
    int b = blockIdx.x, part = blockIdx.y;
    bool vpath = (part < 2);

#pragma unroll
    for (int j = 0; j < 4; j++) {
        int idx4 = tid + j * 256;
        int r = idx4 >> 4, c4 = idx4 & 15;
        if (vpath) {
            ((float4*)wmat)[r * 17 + c4] = ((const float4*)pw)[idx4];
        } else {
            float4 v = ((const float4*)qw)[idx4];
            wmat[(c4 * 4 + 0) * 68 + r] = v.x;
            wmat[(c4 * 4 + 1) * 68 + r] = v.y;
            wmat[(c4 * 4 + 2) * 68 + r] = v.z;
            wmat[(c4 * 4 + 3) * 68 + r] = v.w;
        }
    }
    if (tid < 64) qb_s[tid] = qb[tid];
    __syncthreads();

    int m = tid;
    u64 rr[32];
    {
        const float* src = vpath ? (g_V + (b * 256 + m) * 64) : (g_K + (b * 256 + m) * 64);
        const ulonglong2* s2 = (const ulonglong2*)src;
#pragma unroll
        for (int j = 0; j < 16; j++) { ulonglong2 v = s2[j]; rr[2*j] = v.x; rr[2*j+1] = v.y; }
    }

    if (!vpath) {
        if (part == 2) {
            u64 acc = pk2(0.f, 0.f);
            const ulonglong2* qbp = (const ulonglong2*)qb_s;
#pragma unroll
            for (int j = 0; j < 16; j++) { ulonglong2 v = qbp[j]; fma2(acc, rr[2*j], v.x); fma2(acc, rr[2*j+1], v.y); }
            float2 f = upk2(acc);
            g_kb2[b * 256 + m] = QSCALE * (f.x + f.y);
        }
        int i0 = (part - 2) * 32;
        for (int ii = 0; ii < 32; ii++) {
            int i = i0 + ii;
            u64 acc = pk2(0.f, 0.f);
            const ulonglong2* qp = (const ulonglong2*)&wmat[i * 68];
#pragma unroll
            for (int j = 0; j < 16; j++) { ulonglong2 v = qp[j]; fma2(acc, rr[2*j], v.x); fma2(acc, rr[2*j+1], v.y); }
            float2 f = upk2(acc);
            g_K2T[(b * 64 + i) * 256 + m] = QSCALE * (f.x + f.y);
        }
    } else {
        int c0 = part * 32;
        for (int cc = 0; cc < 32; cc++) {
            int c = c0 + cc;
            u64 acc = pk2(0.f, 0.f);
            const ulonglong2* pp = (const ulonglong2*)&wmat[c * 68];
#pragma unroll
            for (int j = 0; j < 16; j++) { ulonglong2 v = pp[j]; fma2(acc, rr[2*j], v.x); fma2(acc, rr[2*j+1], v.y); }
            float2 f = upk2(acc);
            float val = f.x + f.y;
            g_V2[(b * 256 + m) * 64 + c] = val;
            red[cc * 257 + m] = val;
        }
        __syncthreads();
        int c = tid >> 3, seg = tid & 7;
        float s = 0.f;
#pragma unroll
        for (int j = 0; j < 32; j++) s += red[c * 257 + seg * 32 + j];
#pragma unroll
        for (int o = 4; o; o >>= 1) s += __shfl_down_sync(0xffffffffu, s, o, 8);
        if (seg == 0) g_colsum[b * 64 + c0 + c] = s;
    }
}

// ============================================================
// Kernel 3: mma.sync tf32 attention. 256 threads (8 warps).
// Warp w owns query rows [16w,16w+16) of the 128-query tile.
// Per chunk of 64 keys: QK (16x64) -> exp -> warp-private P -> PV accumulate.
// ============================================================
namespace {
constexpr int TPC = 2;                       // tiles per CTA
// float offsets in dynamic smem
constexpr int F_XS  = 0;                     // Xs[128][68]
constexpr int F_K2T = F_XS  + 128 * 68;      // K2Ts[64][264]
constexpr int F_V2  = F_K2T + 64 * 264;      // V2s[256][72]
constexpr int F_P   = F_V2  + 256 * 72;      // P: 8 warps x [16][68]
constexpr int F_KB  = F_P   + 8 * 16 * 68;   // kb2[256]
constexpr int F_CS  = F_KB  + 256;           // colsum[64]
constexpr int F_PB  = F_CS  + 64;            // pb[64]
constexpr int ATTN_FLOATS = F_PB + 64;       // 53120
constexpr int ATTN_BYTES  = ATTN_FLOATS * 4; // 212480
}

__global__ void __launch_bounds__(256, 1) k_attn4(
    const float* __restrict__ x, const float* __restrict__ pb,
    float* __restrict__ out)
{
    extern __shared__ float sm[];
    int tid  = threadIdx.x;
    int w    = tid >> 5, lane = tid & 31;
    int g    = lane >> 2, tig = lane & 3;
    int b    = blockIdx.y;

    // ---- per-batch staging ----
#pragma unroll
    for (int j = 0; j < 16; j++) {               // K2T: 64 x 256, pitch 264
        int idx4 = tid + j * 256;
        int row = idx4 >> 6, c4 = idx4 & 63;
        *(float4*)&sm[F_K2T + row * 264 + c4 * 4] =
            ((const float4*)g_K2T)[(b * 64 + row) * 64 + c4];
    }
#pragma unroll
    for (int j = 0; j < 16; j++) {               // V2: 256 x 64, pitch 72
        int idx4 = tid + j * 256;
        int row = idx4 >> 4, c4 = idx4 & 15;
        *(float4*)&sm[F_V2 + row * 72 + c4 * 4] =
            ((const float4*)g_V2)[(b * 256 + row) * 16 + c4];
    }
    sm[F_KB + tid] = g_kb2[b * 256 + tid];
    if (tid < 64) {
        sm[F_CS + tid] = g_colsum[b * 64 + tid];
        sm[F_PB + tid] = pb[tid];
    }

    const float* K2Ts = sm + F_K2T;
    const float* V2s  = sm + F_V2;
    const float* kb2s = sm + F_KB;
    float*       Pw   = sm + F_P + w * 16 * 68;

    for (int t = 0; t < TPC; t++) {
        int q0 = (blockIdx.x * TPC + t) * 128;
        __syncthreads();                          // Xs free (covers staging too)
#pragma unroll
        for (int j = 0; j < 8; j++) {             // Xs: 128 x 64, pitch 68
            int idx4 = tid + j * 256;
            int row = idx4 >> 4, c4 = idx4 & 15;
            *(float4*)&sm[F_XS + row * 68 + c4 * 4] =
                ((const float4*)x)[(size_t)(b * NN + q0 + row) * 16 + c4];
        }
        __syncthreads();

        float of[8][4];
#pragma unroll
        for (int nt = 0; nt < 8; nt++)
#pragma unroll
            for (int i = 0; i < 4; i++) of[nt][i] = 0.f;
        float rs0 = 0.f, rs1 = 0.f;

        const float* xr = sm + F_XS + (16 * w + g) * 68;

#pragma unroll
        for (int ch = 0; ch < 4; ch++) {
            int m0 = ch * 64;
            // ---- QK chunk: S[16 x 64] ----
            float sf[8][4];
#pragma unroll
            for (int nt = 0; nt < 8; nt++)
#pragma unroll
                for (int i = 0; i < 4; i++) sf[nt][i] = 0.f;
#pragma unroll
            for (int ks = 0; ks < 8; ks++) {
                int kk = ks * 8 + tig;
                u32 a0 = __float_as_uint(xr[kk]);
                u32 a1 = __float_as_uint(xr[8 * 68 + kk]);
                u32 a2 = __float_as_uint(xr[kk + 4]);
                u32 a3 = __float_as_uint(xr[8 * 68 + kk + 4]);
                const float* b0p = K2Ts + kk * 264 + m0 + g;
                const float* b1p = b0p + 4 * 264;
#pragma unroll
                for (int nt = 0; nt < 8; nt++) {
                    u32 b0 = __float_as_uint(b0p[nt * 8]);
                    u32 b1 = __float_as_uint(b1p[nt * 8]);
                    mma1688(sf[nt], a0, a1, a2, a3, b0, b1);
                }
            }
            // ---- exp(S + kb2) - 1 -> P (warp-private) ----
#pragma unroll
            for (int nt = 0; nt < 8; nt++) {
                int mc = m0 + nt * 8 + 2 * tig;
                float k0 = kb2s[mc], k1 = kb2s[mc + 1];
                float e0 = __expf(sf[nt][0] + k0) - 1.f;
                float e1 = __expf(sf[nt][1] + k1) - 1.f;
                float e2 = __expf(sf[nt][2] + k0) - 1.f;
                float e3 = __expf(sf[nt][3] + k1) - 1.f;
                rs0 += e0 + e1;
                rs1 += e2 + e3;
                int pc = nt * 8 + 2 * tig;
                *(float2*)&Pw[g * 68 + pc]       = make_float2(e0, e1);
                *(float2*)&Pw[(g + 8) * 68 + pc] = make_float2(e2, e3);
            }
            __syncwarp();
            // ---- PV chunk: O += P[16 x 64] @ V2[64 x 64] ----
#pragma unroll
            for (int ks = 0; ks < 8; ks++) {
                int kk = ks * 8 + tig;
                u32 a0 = __float_as_uint(Pw[g * 68 + kk]);
                u32 a1 = __float_as_uint(Pw[(g + 8) * 68 + kk]);
                u32 a2 = __float_as_uint(Pw[g * 68 + kk + 4]);
                u32 a3 = __float_as_uint(Pw[(g + 8) * 68 + kk + 4]);
                const float* b0p = V2s + (m0 + kk) * 72 + g;
                const float* b1p = b0p + 4 * 72;
#pragma unroll
                for (int nt = 0; nt < 8; nt++) {
                    u32 b0 = __float_as_uint(b0p[nt * 8]);
                    u32 b1 = __float_as_uint(b1p[nt * 8]);
                    mma1688(of[nt], a0, a1, a2, a3, b0, b1);
                }
            }
            __syncwarp();                          // P reused next chunk
        }

        // ---- normalize + epilogue ----
        rs0 += __shfl_xor_sync(0xffffffffu, rs0, 1);
        rs0 += __shfl_xor_sync(0xffffffffu, rs0, 2);
        rs1 += __shfl_xor_sync(0xffffffffu, rs1, 1);
        rs1 += __shfl_xor_sync(0xffffffffu, rs1, 2);
        float inv0 = 1.f / (256.f + rs0);
        float inv1 = 1.f / (256.f + rs1);

        int qa = q0 + 16 * w + g;
        int qb_ = qa + 8;
#pragma unroll
        for (int nt = 0; nt < 8; nt++) {
            int c = nt * 8 + 2 * tig;
            float cs0 = sm[F_CS + c], cs1 = sm[F_CS + c + 1];
            float pb0 = sm[F_PB + c], pb1 = sm[F_PB + c + 1];
            *(float2*)&out[(size_t)(b * NN + qa) * 64 + c] =
                make_float2((cs0 + of[nt][0]) * inv0 + pb0,
                            (cs1 + of[nt][1]) * inv0 + pb1);
            *(float2*)&out[(size_t)(b * NN + qb_) * 64 + c] =
                make_float2((cs0 + of[nt][2]) * inv1 + pb0,
                            (cs1 + of[nt][3]) * inv1 + pb1);
        }
    }
}

// ============================================================
extern "C" void kernel_launch(void* const* d_in, const int* in_sizes, int n_in,
                              void* d_out, int out_size) {
    const float* x   = (const float*)d_in[0];
    const float* srw = (const float*)d_in[1];
    const float* srb = (const float*)d_in[2];
    const float* lng = (const float*)d_in[3];
    const float* lnb = (const float*)d_in[4];
    const float* qw  = (const float*)d_in[5];
    const float* qb  = (const float*)d_in[6];
    const float* kvw = (const float*)d_in[7];
    const float* kvb = (const float*)d_in[8];
    const float* pw  = (const float*)d_in[9];
    const float* pb  = (const float*)d_in[10];
    float* out = (float*)d_out;

    k_wtrans<<<1024, 256>>>(srw);
    k_conv<<<dim3(64, 4), 256>>>(x);
    k_lnkv<<<32, 256>>>(srb, lng, lnb, kvw, kvb);
    k_fold<<<dim3(8, 4), 256>>>(qw, qb, pw);
    cudaFuncSetAttribute(k_attn4, cudaFuncAttributeMaxDynamicSharedMemorySize, ATTN_BYTES);
    k_attn4<<<dim3(NN / (128 * TPC), NB), 256, ATTN_BYTES>>>(x, pb, out);
}

// round 5
// speedup vs baseline: 6.0866x; 1.2673x over previous
#include <cuda_runtime.h>
#include <cstdint>
#include <cstddef>

// EfficientSelfAttention: B=8, N=16384 (128x128), C=64, heads=1, SR=8 -> Nr=256
// R5: mma-B operands prepacked in fragment order; A-frags hoisted; conv v2
// (transposed A staging, split-k 8); fold v2 (split accumulators, packed out).

namespace {
constexpr int   NB     = 8;
constexpr int   NN     = 16384;
constexpr float QSCALE = 0.125f;   // 64^-0.5
}

// ---- scratch ----
__device__ float g_wT[64 * 64 * 64];      // [k][oc]
__device__ float g_part[8 * 2048 * 64];   // conv split-k partials
__device__ float g_K[8 * 256 * 64];
__device__ float g_V[8 * 256 * 64];
__device__ float g_K2p[8 * 16384];        // QK B-frag pack [b][ch][ks][lane][nt2]
__device__ float g_V2p[8 * 16384];        // PV B-frag pack
__device__ float g_kb2[8 * 256];
__device__ float g_colsum[8 * 64];

using u64 = unsigned long long;
using u32 = unsigned int;

__device__ __forceinline__ u64 pk2(float x, float y) {
    u64 r; asm("mov.b64 %0,{%1,%2};" : "=l"(r) : "f"(x), "f"(y)); return r;
}
__device__ __forceinline__ float2 upk2(u64 v) {
    float2 f; asm("mov.b64 {%0,%1},%2;" : "=f"(f.x), "=f"(f.y) : "l"(v)); return f;
}
__device__ __forceinline__ void fma2(u64 &d, u64 a, u64 b) {
    asm("fma.rn.f32x2 %0,%1,%2,%0;" : "+l"(d) : "l"(a), "l"(b));
}
__device__ __forceinline__ void mma1688(float* d, u32 a0, u32 a1, u32 a2, u32 a3,
                                        u32 b0, u32 b1) {
    asm volatile(
        "mma.sync.aligned.m16n8k8.row.col.f32.tf32.tf32.f32 "
        "{%0,%1,%2,%3}, {%4,%5,%6,%7}, {%8,%9}, {%0,%1,%2,%3};"
        : "+f"(d[0]), "+f"(d[1]), "+f"(d[2]), "+f"(d[3])
        : "r"(a0), "r"(a1), "r"(a2), "r"(a3), "r"(b0), "r"(b1));
}

// ============================================================
// Kernel 1a: transpose sr_w -> wT[k][oc]
// ============================================================
__global__ void k_wtrans(const float* __restrict__ srw) {
    int d   = blockIdx.x * 256 + threadIdx.x;
    int oc  = d & 63;
    int k   = d >> 6;
    int ic  = k & 63;
    int pix = k >> 6;
    g_wT[d] = srw[(oc << 12) + (ic << 6) + pix];
}

// ============================================================
// Kernel 1b: conv v2. CTA = 64 pos x 64 oc, split-k 8 (512 k = 8 pixels),
// 8 chunks of 64 k (= 1 pixel x 64 ic). A staged transposed [k][pos].
// grid (32, 8), 256 threads; thread (to=tid&15, tp=tid>>4) -> 4 pos x 4 oc.
// ============================================================
__global__ void __launch_bounds__(256) k_conv(const float* __restrict__ x) {
    __shared__ float A_sT[64 * 68];   // [k_local][pos]
    __shared__ float W_s[64 * 68];    // [k_local][oc]
    int tid = threadIdx.x;
    int pt = blockIdx.x, kt = blockIdx.y;
    int to = tid & 15, tp = tid >> 4;

    u64 acc[4][2];
#pragma unroll
    for (int r = 0; r < 4; r++) { acc[r][0] = pk2(0.f, 0.f); acc[r][1] = pk2(0.f, 0.f); }

    for (int ck = 0; ck < 8; ck++) {
        int pix = kt * 8 + ck;
        int kb  = pix * 64;
        // stage W chunk: wT rows [kb, kb+64), 64 oc
#pragma unroll
        for (int j = 0; j < 4; j++) {
            int lin = tid + j * 256;            // 1024 float4
            int row = lin >> 4, c4 = lin & 15;
            *(float4*)&W_s[row * 68 + c4 * 4] = ((const float4*)(g_wT + kb * 64))[lin];
        }
        // stage A transposed: 64 pos x 64 ic (one pixel)
#pragma unroll
        for (int j = 0; j < 4; j++) {
            int lin = tid + j * 256;
            int c4 = lin & 15, i = lin >> 4;    // i = pos_local
            int pos = pt * 64 + i;
            int b = pos >> 8, pp = pos & 255;
            int oh = pp >> 4, ow = pp & 15;
            int row = oh * 8 + (pix >> 3);
            int col = ow * 8 + (pix & 7);
            float4 v = ((const float4*)x)[(size_t)(b * 16384 + row * 128 + col) * 16 + c4];
            A_sT[(c4 * 4 + 0) * 68 + i] = v.x;
            A_sT[(c4 * 4 + 1) * 68 + i] = v.y;
            A_sT[(c4 * 4 + 2) * 68 + i] = v.z;
            A_sT[(c4 * 4 + 3) * 68 + i] = v.w;
        }
        __syncthreads();
#pragma unroll 4
        for (int kk = 0; kk < 64; kk++) {
            float4 av = *(const float4*)&A_sT[kk * 68 + tp * 4];
            ulonglong2 wv = *(const ulonglong2*)&W_s[kk * 68 + to * 4];
            u64 a0 = pk2(av.x, av.x), a1 = pk2(av.y, av.y);
            u64 a2 = pk2(av.z, av.z), a3 = pk2(av.w, av.w);
            fma2(acc[0][0], a0, wv.x); fma2(acc[0][1], a0, wv.y);
            fma2(acc[1][0], a1, wv.x); fma2(acc[1][1], a1, wv.y);
            fma2(acc[2][0], a2, wv.x); fma2(acc[2][1], a2, wv.y);
            fma2(acc[3][0], a3, wv.x); fma2(acc[3][1], a3, wv.y);
        }
        __syncthreads();
    }
    int pos0 = pt * 64 + tp * 4;
#pragma unroll
    for (int r = 0; r < 4; r++) {
        float2 f0 = upk2(acc[r][0]), f1 = upk2(acc[r][1]);
        ((float4*)g_part)[(kt * 2048 + pos0 + r) * 16 + to] =
            make_float4(f0.x, f0.y, f1.x, f1.y);
    }
}

// ============================================================
// Kernel 2: sum 8 partials + bias -> LayerNorm -> KV projection
// ============================================================
__global__ void __launch_bounds__(256) k_lnkv(
    const float* __restrict__ srb, const float* __restrict__ lng,
    const float* __restrict__ lnb, const float* __restrict__ kvw,
    const float* __restrict__ kvb)
{
    __shared__ float kvw_s[128 * 68];
    __shared__ float xn_s[8 * 68];
    __shared__ float kvb_s[128], srb_s[64], lg_s[64], lb_s[64];
    int tid = threadIdx.x;
#pragma unroll
    for (int j = 0; j < 8; j++) {
        int idx4 = tid + j * 256;
        int r = idx4 >> 4, c4 = idx4 & 15;
        ((float4*)kvw_s)[r * 17 + c4] = ((const float4*)kvw)[idx4];
    }
    if (tid < 128) kvb_s[tid] = kvb[tid];
    if (tid >= 128 && tid < 192) {
        int c = tid - 128;
        srb_s[c] = srb[c]; lg_s[c] = lng[c]; lb_s[c] = lnb[c];
    }
    __syncthreads();

    int w = tid >> 5, lane = tid & 31;
    for (int t = 0; t < 8; t++) {
        int row = blockIdx.x * 64 + w * 8 + t;
        int c0 = lane, c1 = lane + 32;
        float v0 = srb_s[c0], v1 = srb_s[c1];
#pragma unroll
        for (int kt = 0; kt < 8; kt++) {
            v0 += g_part[kt * 131072 + row * 64 + c0];
            v1 += g_part[kt * 131072 + row * 64 + c1];
        }
        float s = v0 + v1, sq = v0 * v0 + v1 * v1;
#pragma unroll
        for (int o = 16; o; o >>= 1) {
            s  += __shfl_xor_sync(0xffffffffu, s, o);
            sq += __shfl_xor_sync(0xffffffffu, sq, o);
        }
        float mu  = s * (1.f / 64.f);
        float var = sq * (1.f / 64.f) - mu * mu;
        float inv = rsqrtf(var + 1e-5f);
        xn_s[w * 68 + c0] = (v0 - mu) * inv * lg_s[c0] + lb_s[c0];
        xn_s[w * 68 + c1] = (v1 - mu) * inv * lg_s[c1] + lb_s[c1];
        __syncwarp();
#pragma unroll
        for (int rr = 0; rr < 4; rr++) {
            int r = lane + rr * 32;
            u64 acc0 = pk2(0.f, 0.f), acc1 = pk2(0.f, 0.f);
#pragma unroll
            for (int c4 = 0; c4 < 8; c4++) {
                ulonglong2 wv0 = *(const ulonglong2*)&kvw_s[r * 68 + c4 * 8];
                ulonglong2 xv0 = *(const ulonglong2*)&xn_s[w * 68 + c4 * 8];
                ulonglong2 wv1 = *(const ulonglong2*)&kvw_s[r * 68 + c4 * 8 + 4];
                ulonglong2 xv1 = *(const ulonglong2*)&xn_s[w * 68 + c4 * 8 + 4];
                fma2(acc0, wv0.x, xv0.x); fma2(acc1, wv0.y, xv0.y);
                fma2(acc0, wv1.x, xv1.x); fma2(acc1, wv1.y, xv1.y);
            }
            float2 f0 = upk2(acc0), f1 = upk2(acc1);
            float val = f0.x + f0.y + f1.x + f1.y + kvb_s[r];
            if (r < 64) g_K[row * 64 + r] = val;
            else        g_V[row * 64 + (r - 64)] = val;
        }
        __syncwarp();
    }
}

// ============================================================
// Kernel 2b: fold projections, emit mma-fragment-packed operands.
// grid (8 batch, 4 part), 256 threads (thread = key m).
//  parts 0,1: V pack c[0:32)/[32:64) + colsum;  parts 2,3: K pack i[0:32)/[32:64) (+kb2 on 2)
// pack float index (per batch) for (i-or-m slot, n-col):
//   K: i=(ks,tig,h), n=m: ((ch*8+ks)*32 + g*4+tig)*16 + nt*2 + h
// ============================================================
__global__ void __launch_bounds__(256) k_fold(
    const float* __restrict__ qw, const float* __restrict__ qb,
    const float* __restrict__ pw)
{
    __shared__ float wmat[64 * 68];
    __shared__ float red[32 * 257];
    __shared__ float qb_s[64];
    int tid = threadIdx.x;
    int b = blockIdx.x, part = blockIdx.y;
    bool vpath = (part < 2);

#pragma unroll
    for (int j = 0; j < 4; j++) {
        int idx4 = tid + j * 256;
        int r = idx4 >> 4, c4 = idx4 & 15;
        if (vpath) {
            ((float4*)wmat)[r * 17 + c4] = ((const float4*)pw)[idx4];
        } else {
            float4 v = ((const float4*)qw)[idx4];
            wmat[(c4 * 4 + 0) * 68 + r] = v.x;
            wmat[(c4 * 4 + 1) * 68 + r] = v.y;
            wmat[(c4 * 4 + 2) * 68 + r] = v.z;
            wmat[(c4 * 4 + 3) * 68 + r] = v.w;
        }
    }
    if (tid < 64) qb_s[tid] = qb[tid];
    __syncthreads();

    int m = tid;
    u64 rr[32];
    {
        const float* src = vpath ? (g_V + (b * 256 + m) * 64) : (g_K + (b * 256 + m) * 64);
        const ulonglong2* s2 = (const ulonglong2*)src;
#pragma unroll
        for (int j = 0; j < 16; j++) { ulonglong2 v = s2[j]; rr[2*j] = v.x; rr[2*j+1] = v.y; }
    }

    if (!vpath) {
        if (part == 2) {
            u64 a0 = pk2(0.f, 0.f), a1 = pk2(0.f, 0.f);
            const ulonglong2* qbp = (const ulonglong2*)qb_s;
#pragma unroll
            for (int j = 0; j < 16; j++) { ulonglong2 v = qbp[j]; fma2(a0, rr[2*j], v.x); fma2(a1, rr[2*j+1], v.y); }
            float2 f0 = upk2(a0), f1 = upk2(a1);
            g_kb2[b * 256 + m] = QSCALE * (f0.x + f0.y + f1.x + f1.y);
        }
        int ch = m >> 6, rm = m & 63, nt = rm >> 3, gg = rm & 7;
        int i0 = (part - 2) * 32;
        for (int ii = 0; ii < 32; ii++) {
            int i = i0 + ii;
            u64 a0 = pk2(0.f, 0.f), a1 = pk2(0.f, 0.f);
            const ulonglong2* qp = (const ulonglong2*)&wmat[i * 68];
#pragma unroll
            for (int j = 0; j < 16; j++) { ulonglong2 v = qp[j]; fma2(a0, rr[2*j], v.x); fma2(a1, rr[2*j+1], v.y); }
            float2 f0 = upk2(a0), f1 = upk2(a1);
            int ks = i >> 3, t = i & 7, tig = t & 3, h = t >> 2;
            g_K2p[b * 16384 + ((ch * 8 + ks) * 32 + gg * 4 + tig) * 16 + nt * 2 + h] =
                QSCALE * (f0.x + f0.y + f1.x + f1.y);
        }
    } else {
        int ch = m >> 6, km = m & 63, ks = km >> 3, tt = km & 7, tig = tt & 3, h = tt >> 2;
        int c0 = part * 32;
        for (int cc = 0; cc < 32; cc++) {
            int c = c0 + cc;
            u64 a0 = pk2(0.f, 0.f), a1 = pk2(0.f, 0.f);
            const ulonglong2* pp = (const ulonglong2*)&wmat[c * 68];
#pragma unroll
            for (int j = 0; j < 16; j++) { ulonglong2 v = pp[j]; fma2(a0, rr[2*j], v.x); fma2(a1, rr[2*j+1], v.y); }
            float2 f0 = upk2(a0), f1 = upk2(a1);
            float val = f0.x + f0.y + f1.x + f1.y;
            int nt = c >> 3, gg = c & 7;
            g_V2p[b * 16384 + ((ch * 8 + ks) * 32 + gg * 4 + tig) * 16 + nt * 2 + h] = val;
            red[cc * 257 + m] = val;
        }
        __syncthreads();
        int c = tid >> 3, seg = tid & 7;
        float s = 0.f;
#pragma unroll
        for (int j = 0; j < 32; j++) s += red[c * 257 + seg * 32 + j];
#pragma unroll
        for (int o = 4; o; o >>= 1) s += __shfl_down_sync(0xffffffffu, s, o, 8);
        if (seg == 0) g_colsum[b * 64 + c0 + c] = s;
    }
}

// ============================================================
// Kernel 3: mma.sync tf32 attention with fragment-packed B operands.
// 256 threads (8 warps); warp owns 16 query rows; A-frags hoisted to regs;
// B loads: 4x LDS.128 per ks (lane-pitch 20 floats => conflict-free).
// ============================================================
namespace {
constexpr int TPC   = 2;
constexpr int F_K2  = 0;                       // 4*8*32*20 = 20480 floats
constexpr int F_V2  = 20480;                   // 20480
constexpr int F_XS  = 40960;                   // Xs[128][68] = 8704, reused as P
constexpr int F_KB  = 49664;                   // kb2[256]
constexpr int F_CS  = 49920;                   // colsum[64]
constexpr int F_PB  = 49984;                   // pb[64]
constexpr int ATTN_FLOATS = 50048;
constexpr int ATTN_BYTES  = ATTN_FLOATS * 4;   // 200192
}

__global__ void __launch_bounds__(256, 1) k_attn5(
    const float* __restrict__ x, const float* __restrict__ pb,
    float* __restrict__ out)
{
    extern __shared__ float sm[];
    int tid  = threadIdx.x;
    int w    = tid >> 5, lane = tid & 31;
    int g    = lane >> 2, tig = lane & 3;
    int b    = blockIdx.y;

    // ---- per-batch staging: packed operands into pitch-20 lanes ----
    float4* k2d = (float4*)(sm + F_K2);
    float4* v2d = (float4*)(sm + F_V2);
    const float4* k2s = (const float4*)g_K2p + b * 4096;
    const float4* v2s = (const float4*)g_V2p + b * 4096;
#pragma unroll
    for (int j = 0; j < 16; j++) {
        int idx4 = tid + j * 256;                // 4096 float4
        int entry = idx4 >> 2, jj = idx4 & 3;
        k2d[entry * 5 + jj] = k2s[idx4];
        v2d[entry * 5 + jj] = v2s[idx4];
    }
    sm[F_KB + tid] = g_kb2[b * 256 + tid];
    if (tid < 64) {
        sm[F_CS + tid] = g_colsum[b * 64 + tid];
        sm[F_PB + tid] = pb[tid];
    }

    const float* kb2s = sm + F_KB;
    float*       Pw   = sm + F_XS + w * 16 * 68;

    for (int t = 0; t < TPC; t++) {
        int q0 = (blockIdx.x * TPC + t) * 128;
        __syncthreads();                          // prior tile P done (+ first: staging)
#pragma unroll
        for (int j = 0; j < 8; j++) {             // Xs: 128 x 64, pitch 68
            int idx4 = tid + j * 256;
            int row = idx4 >> 4, c4 = idx4 & 15;
            *(float4*)&sm[F_XS + row * 68 + c4 * 4] =
                ((const float4*)x)[(size_t)(b * NN + q0 + row) * 16 + c4];
        }
        __syncthreads();

        // ---- hoist A fragments (warp-own rows only) ----
        u32 ah0[8], ah1[8], ah2[8], ah3[8];
        {
            const float* xr = sm + F_XS + (16 * w + g) * 68;
#pragma unroll
            for (int ks = 0; ks < 8; ks++) {
                int kk = ks * 8 + tig;
                ah0[ks] = __float_as_uint(xr[kk]);
                ah1[ks] = __float_as_uint(xr[8 * 68 + kk]);
                ah2[ks] = __float_as_uint(xr[kk + 4]);
                ah3[ks] = __float_as_uint(xr[8 * 68 + kk + 4]);
            }
        }

        float of[8][4];
#pragma unroll
        for (int nt = 0; nt < 8; nt++)
#pragma unroll
            for (int i = 0; i < 4; i++) of[nt][i] = 0.f;
        float rs0 = 0.f, rs1 = 0.f;

#pragma unroll
        for (int ch = 0; ch < 4; ch++) {
            // ---- QK chunk ----
            float sf[8][4];
#pragma unroll
            for (int nt = 0; nt < 8; nt++)
#pragma unroll
                for (int i = 0; i < 4; i++) sf[nt][i] = 0.f;
#pragma unroll
            for (int ks = 0; ks < 8; ks++) {
                const float4* bp = (const float4*)(sm + F_K2) + ((ch * 8 + ks) * 32 + lane) * 5;
                float4 B0 = bp[0], B1 = bp[1], B2 = bp[2], B3 = bp[3];
                u32 a0 = ah0[ks], a1 = ah1[ks], a2 = ah2[ks], a3 = ah3[ks];
                mma1688(sf[0], a0, a1, a2, a3, __float_as_uint(B0.x), __float_as_uint(B0.y));
                mma1688(sf[1], a0, a1, a2, a3, __float_as_uint(B0.z), __float_as_uint(B0.w));
                mma1688(sf[2], a0, a1, a2, a3, __float_as_uint(B1.x), __float_as_uint(B1.y));
                mma1688(sf[3], a0, a1, a2, a3, __float_as_uint(B1.z), __float_as_uint(B1.w));
                mma1688(sf[4], a0, a1, a2, a3, __float_as_uint(B2.x), __float_as_uint(B2.y));
                mma1688(sf[5], a0, a1, a2, a3, __float_as_uint(B2.z), __float_as_uint(B2.w));
                mma1688(sf[6], a0, a1, a2, a3, __float_as_uint(B3.x), __float_as_uint(B3.y));
                mma1688(sf[7], a0, a1, a2, a3, __float_as_uint(B3.z), __float_as_uint(B3.w));
            }
            // ---- exp(S + kb2) - 1 -> P ----
            int m0 = ch * 64;
#pragma unroll
            for (int nt = 0; nt < 8; nt++) {
                int mc = m0 + nt * 8 + 2 * tig;
                float k0 = kb2s[mc], k1 = kb2s[mc + 1];
                float e0 = __expf(sf[nt][0] + k0) - 1.f;
                float e1 = __expf(sf[nt][1] + k1) - 1.f;
                float e2 = __expf(sf[nt][2] + k0) - 1.f;
                float e3 = __expf(sf[nt][3] + k1) - 1.f;
                rs0 += e0 + e1;
                rs1 += e2 + e3;
                int pc = nt * 8 + 2 * tig;
                *(float2*)&Pw[g * 68 + pc]       = make_float2(e0, e1);
                *(float2*)&Pw[(g + 8) * 68 + pc] = make_float2(e2, e3);
            }
            __syncwarp();
            // ---- PV chunk ----
#pragma unroll
            for (int ks = 0; ks < 8; ks++) {
                int kk = ks * 8 + tig;
                u32 a0 = __float_as_uint(Pw[g * 68 + kk]);
                u32 a1 = __float_as_uint(Pw[(g + 8) * 68 + kk]);
                u32 a2 = __float_as_uint(Pw[g * 68 + kk + 4]);
                u32 a3 = __float_as_uint(Pw[(g + 8) * 68 + kk + 4]);
                const float4* vp = (const float4*)(sm + F_V2) + ((ch * 8 + ks) * 32 + lane) * 5;
                float4 C0 = vp[0], C1 = vp[1], C2 = vp[2], C3 = vp[3];
                mma1688(of[0], a0, a1, a2, a3, __float_as_uint(C0.x), __float_as_uint(C0.y));
                mma1688(of[1], a0, a1, a2, a3, __float_as_uint(C0.z), __float_as_uint(C0.w));
                mma1688(of[2], a0, a1, a2, a3, __float_as_uint(C1.x), __float_as_uint(C1.y));
                mma1688(of[3], a0, a1, a2, a3, __float_as_uint(C1.z), __float_as_uint(C1.w));
                mma1688(of[4], a0, a1, a2, a3, __float_as_uint(C2.x), __float_as_uint(C2.y));
                mma1688(of[5], a0, a1, a2, a3, __float_as_uint(C2.z), __float_as_uint(C2.w));
                mma1688(of[6], a0, a1, a2, a3, __float_as_uint(C3.x), __float_as_uint(C3.y));
                mma1688(of[7], a0, a1, a2, a3, __float_as_uint(C3.z), __float_as_uint(C3.w));
            }
            __syncwarp();                          // P reused next chunk
        }

        // ---- normalize + epilogue ----
        rs0 += __shfl_xor_sync(0xffffffffu, rs0, 1);
        rs0 += __shfl_xor_sync(0xffffffffu, rs0, 2);
        rs1 += __shfl_xor_sync(0xffffffffu, rs1, 1);
        rs1 += __shfl_xor_sync(0xffffffffu, rs1, 2);
        float inv0 = 1.f / (256.f + rs0);
        float inv1 = 1.f / (256.f + rs1);

        int qa  = q0 + 16 * w + g;
        int qb_ = qa + 8;
#pragma unroll
        for (int nt = 0; nt < 8; nt++) {
            int c = nt * 8 + 2 * tig;
            float cs0 = sm[F_CS + c], cs1 = sm[F_CS + c + 1];
            float pb0 = sm[F_PB + c], pb1 = sm[F_PB + c + 1];
            *(float2*)&out[(size_t)(b * NN + qa) * 64 + c] =
                make_float2((cs0 + of[nt][0]) * inv0 + pb0,
                            (cs1 + of[nt][1]) * inv0 + pb1);
            *(float2*)&out[(size_t)(b * NN + qb_) * 64 + c] =
                make_float2((cs0 + of[nt][2]) * inv1 + pb0,
                            (cs1 + of[nt][3]) * inv1 + pb1);
        }
    }
}

// ============================================================
extern "C" void kernel_launch(void* const* d_in, const int* in_sizes, int n_in,
                              void* d_out, int out_size) {
    const float* x   = (const float*)d_in[0];
    const float* srw = (const float*)d_in[1];
    const float* srb = (const float*)d_in[2];
    const float* lng = (const float*)d_in[3];
    const float* lnb = (const float*)d_in[4];
    const float* qw  = (const float*)d_in[5];
    const float* qb  = (const float*)d_in[6];
    const float* kvw = (const float*)d_in[7];
    const float* kvb = (const float*)d_in[8];
    const float* pw  = (const float*)d_in[9];
    const float* pb  = (const float*)d_in[10];
    float* out = (float*)d_out;

    k_wtrans<<<1024, 256>>>(srw);
    k_conv<<<dim3(32, 8), 256>>>(x);
    k_lnkv<<<32, 256>>>(srb, lng, lnb, kvw, kvb);
    k_fold<<<dim3(8, 4), 256>>>(qw, qb, pw);
    cudaFuncSetAttribute(k_attn5, cudaFuncAttributeMaxDynamicSharedMemorySize, ATTN_BYTES);
    k_attn5<<<dim3(NN / (128 * TPC), NB), 256, ATTN_BYTES>>>(x, pb, out);
}

// round 7
// speedup vs baseline: 8.2718x; 1.3590x over previous
#include <cuda_runtime.h>
#include <cuda_bf16.h>
#include <cstdint>
#include <cstddef>

// EfficientSelfAttention: B=8, N=16384 (128x128), C=64, heads=1, SR=8 -> Nr=256
// R6: attention GEMMs on mma.sync.m16n8k16.bf16 (half the mma count of tf32 k8,
// half the operand bytes -> ~100KB smem -> 2 CTAs/SM). E-1 trick keeps the
// dominant colsum term exact fp32; bf16 only carries the small e@V2 term.

namespace {
constexpr int   NB     = 8;
constexpr int   NN     = 16384;
constexpr float QSCALE = 0.125f;   // 64^-0.5
}

// ---- scratch ----
__device__ float g_wT[64 * 64 * 64];      // [k][oc]
__device__ float g_part[8 * 2048 * 64];   // conv split-k partials
__device__ float g_K[8 * 256 * 64];
__device__ float g_V[8 * 256 * 64];
__device__ unsigned int g_K2p[8 * 8192];  // bf16 QK B-frag pack (u32-aligned)
__device__ unsigned int g_V2p[8 * 8192];  // bf16 PV B-frag pack
__device__ float g_kb2[8 * 256];
__device__ float g_colsum[8 * 64];

using u64 = unsigned long long;
using u32 = unsigned int;

__device__ __forceinline__ u64 pk2(float x, float y) {
    u64 r; asm("mov.b64 %0,{%1,%2};" : "=l"(r) : "f"(x), "f"(y)); return r;
}
__device__ __forceinline__ float2 upk2(u64 v) {
    float2 f; asm("mov.b64 {%0,%1},%2;" : "=f"(f.x), "=f"(f.y) : "l"(v)); return f;
}
__device__ __forceinline__ void fma2(u64 &d, u64 a, u64 b) {
    asm("fma.rn.f32x2 %0,%1,%2,%0;" : "+l"(d) : "l"(a), "l"(b));
}
__device__ __forceinline__ u32 bfx2(float lo, float hi) {
    u32 r; asm("cvt.rn.bf16x2.f32 %0, %1, %2;" : "=r"(r) : "f"(hi), "f"(lo)); return r;
}
// bf16 mma: D(16x8 f32) += A(16x16 bf16) * B(16x8 bf16)
__device__ __forceinline__ void mmabf(float* d, u32 a0, u32 a1, u32 a2, u32 a3,
                                      u32 b0, u32 b1) {
    asm volatile(
        "mma.sync.aligned.m16n8k16.row.col.f32.bf16.bf16.f32 "
        "{%0,%1,%2,%3}, {%4,%5,%6,%7}, {%8,%9}, {%0,%1,%2,%3};"
        : "+f"(d[0]), "+f"(d[1]), "+f"(d[2]), "+f"(d[3])
        : "r"(a0), "r"(a1), "r"(a2), "r"(a3), "r"(b0), "r"(b1));
}

// ============================================================
// Kernel 1a: transpose sr_w -> wT[k][oc]
// ============================================================
__global__ void k_wtrans(const float* __restrict__ srw) {
    int d   = blockIdx.x * 256 + threadIdx.x;
    int oc  = d & 63;
    int k   = d >> 6;
    int ic  = k & 63;
    int pix = k >> 6;
    g_wT[d] = srw[(oc << 12) + (ic << 6) + pix];
}

// ============================================================
// Kernel 1b: conv v2 (unchanged from R5 — known good)
// ============================================================
__global__ void __launch_bounds__(256) k_conv(const float* __restrict__ x) {
    __shared__ float A_sT[64 * 68];
    __shared__ float W_s[64 * 68];
    int tid = threadIdx.x;
    int pt = blockIdx.x, kt = blockIdx.y;
    int to = tid & 15, tp = tid >> 4;

    u64 acc[4][2];
#pragma unroll
    for (int r = 0; r < 4; r++) { acc[r][0] = pk2(0.f, 0.f); acc[r][1] = pk2(0.f, 0.f); }

    for (int ck = 0; ck < 8; ck++) {
        int pix = kt * 8 + ck;
        int kb  = pix * 64;
#pragma unroll
        for (int j = 0; j < 4; j++) {
            int lin = tid + j * 256;
            int row = lin >> 4, c4 = lin & 15;
            *(float4*)&W_s[row * 68 + c4 * 4] = ((const float4*)(g_wT + kb * 64))[lin];
        }
#pragma unroll
        for (int j = 0; j < 4; j++) {
            int lin = tid + j * 256;
            int c4 = lin & 15, i = lin >> 4;
            int pos = pt * 64 + i;
            int b = pos >> 8, pp = pos & 255;
            int oh = pp >> 4, ow = pp & 15;
            int row = oh * 8 + (pix >> 3);
            int col = ow * 8 + (pix & 7);
            float4 v = ((const float4*)x)[(size_t)(b * 16384 + row * 128 + col) * 16 + c4];
            A_sT[(c4 * 4 + 0) * 68 + i] = v.x;
            A_sT[(c4 * 4 + 1) * 68 + i] = v.y;
            A_sT[(c4 * 4 + 2) * 68 + i] = v.z;
            A_sT[(c4 * 4 + 3) * 68 + i] = v.w;
        }
        __syncthreads();
#pragma unroll 4
        for (int kk = 0; kk < 64; kk++) {
            float4 av = *(const float4*)&A_sT[kk * 68 + tp * 4];
            ulonglong2 wv = *(const ulonglong2*)&W_s[kk * 68 + to * 4];
            u64 a0 = pk2(av.x, av.x), a1 = pk2(av.y, av.y);
            u64 a2 = pk2(av.z, av.z), a3 = pk2(av.w, av.w);
            fma2(acc[0][0], a0, wv.x); fma2(acc[0][1], a0, wv.y);
            fma2(acc[1][0], a1, wv.x); fma2(acc[1][1], a1, wv.y);
            fma2(acc[2][0], a2, wv.x); fma2(acc[2][1], a2, wv.y);
            fma2(acc[3][0], a3, wv.x); fma2(acc[3][1], a3, wv.y);
        }
        __syncthreads();
    }
    int pos0 = pt * 64 + tp * 4;
#pragma unroll
    for (int r = 0; r < 4; r++) {
        float2 f0 = upk2(acc[r][0]), f1 = upk2(acc[r][1]);
        ((float4*)g_part)[(kt * 2048 + pos0 + r) * 16 + to] =
            make_float4(f0.x, f0.y, f1.x, f1.y);
    }
}

// ============================================================
// Kernel 2: sum 8 partials + bias -> LayerNorm -> KV projection (unchanged)
// ============================================================
__global__ void __launch_bounds__(256) k_lnkv(
    const float* __restrict__ srb, const float* __restrict__ lng,
    const float* __restrict__ lnb, const float* __restrict__ kvw,
    const float* __restrict__ kvb)
{
    __shared__ float kvw_s[128 * 68];
    __shared__ float xn_s[8 * 68];
    __shared__ float kvb_s[128], srb_s[64], lg_s[64], lb_s[64];
    int tid = threadIdx.x;
#pragma unroll
    for (int j = 0; j < 8; j++) {
        int idx4 = tid + j * 256;
        int r = idx4 >> 4, c4 = idx4 & 15;
        ((float4*)kvw_s)[r * 17 + c4] = ((const float4*)kvw)[idx4];
    }
    if (tid < 128) kvb_s[tid] = kvb[tid];
    if (tid >= 128 && tid < 192) {
        int c = tid - 128;
        srb_s[c] = srb[c]; lg_s[c] = lng[c]; lb_s[c] = lnb[c];
    }
    __syncthreads();

    int w = tid >> 5, lane = tid & 31;
    for (int t = 0; t < 8; t++) {
        int row = blockIdx.x * 64 + w * 8 + t;
        int c0 = lane, c1 = lane + 32;
        float v0 = srb_s[c0], v1 = srb_s[c1];
#pragma unroll
        for (int kt = 0; kt < 8; kt++) {
            v0 += g_part[kt * 131072 + row * 64 + c0];
            v1 += g_part[kt * 131072 + row * 64 + c1];
        }
        float s = v0 + v1, sq = v0 * v0 + v1 * v1;
#pragma unroll
        for (int o = 16; o; o >>= 1) {
            s  += __shfl_xor_sync(0xffffffffu, s, o);
            sq += __shfl_xor_sync(0xffffffffu, sq, o);
        }
        float mu  = s * (1.f / 64.f);
        float var = sq * (1.f / 64.f) - mu * mu;
        float inv = rsqrtf(var + 1e-5f);
        xn_s[w * 68 + c0] = (v0 - mu) * inv * lg_s[c0] + lb_s[c0];
        xn_s[w * 68 + c1] = (v1 - mu) * inv * lg_s[c1] + lb_s[c1];
        __syncwarp();
#pragma unroll
        for (int rr = 0; rr < 4; rr++) {
            int r = lane + rr * 32;
            u64 acc0 = pk2(0.f, 0.f), acc1 = pk2(0.f, 0.f);
#pragma unroll
            for (int c4 = 0; c4 < 8; c4++) {
                ulonglong2 wv0 = *(const ulonglong2*)&kvw_s[r * 68 + c4 * 8];
                ulonglong2 xv0 = *(const ulonglong2*)&xn_s[w * 68 + c4 * 8];
                ulonglong2 wv1 = *(const ulonglong2*)&kvw_s[r * 68 + c4 * 8 + 4];
                ulonglong2 xv1 = *(const ulonglong2*)&xn_s[w * 68 + c4 * 8 + 4];
                fma2(acc0, wv0.x, xv0.x); fma2(acc1, wv0.y, xv0.y);
                fma2(acc0, wv1.x, xv1.x); fma2(acc1, wv1.y, xv1.y);
            }
            float2 f0 = upk2(acc0), f1 = upk2(acc1);
            float val = f0.x + f0.y + f1.x + f1.y + kvb_s[r];
            if (r < 64) g_K[row * 64 + r] = val;
            else        g_V[row * 64 + (r - 64)] = val;
        }
        __syncwarp();
    }
}

// ============================================================
// Kernel 2b: fold projections, emit bf16 mma-fragment packs.
// grid (8 batch, 8 part), 256 threads (thread = key m).
//  parts 0-3: V pack, 16 cols each + colsum;  parts 4-7: K pack, 16 i's each (+kb2 on 4)
// u16 index = (((ch*4+ks)*32 + g*4+tig)*16 + nt*2 + h)*2 + j
// ============================================================
__global__ void __launch_bounds__(256) k_fold(
    const float* __restrict__ qw, const float* __restrict__ qb,
    const float* __restrict__ pw)
{
    __shared__ float wmat[64 * 68];
    __shared__ float red[16 * 257];
    __shared__ float qb_s[64];
    int tid = threadIdx.x;
    int b = blockIdx.x, part = blockIdx.y;
    bool vpath = (part < 4);

#pragma unroll
    for (int j = 0; j < 4; j++) {
        int idx4 = tid + j * 256;
        int r = idx4 >> 4, c4 = idx4 & 15;
        if (vpath) {
            ((float4*)wmat)[r * 17 + c4] = ((const float4*)pw)[idx4];
        } else {
            float4 v = ((const float4*)qw)[idx4];
            wmat[(c4 * 4 + 0) * 68 + r] = v.x;
            wmat[(c4 * 4 + 1) * 68 + r] = v.y;
            wmat[(c4 * 4 + 2) * 68 + r] = v.z;
            wmat[(c4 * 4 + 3) * 68 + r] = v.w;
        }
    }
    if (tid < 64) qb_s[tid] = qb[tid];
    __syncthreads();

    int m = tid;
    u64 rr[32];
    {
        const float* src = vpath ? (g_V + (b * 256 + m) * 64) : (g_K + (b * 256 + m) * 64);
        const ulonglong2* s2 = (const ulonglong2*)src;
#pragma unroll
        for (int j = 0; j < 16; j++) { ulonglong2 v = s2[j]; rr[2*j] = v.x; rr[2*j+1] = v.y; }
    }

    if (!vpath) {
        if (part == 4) {
            u64 a0 = pk2(0.f, 0.f), a1 = pk2(0.f, 0.f);
            const ulonglong2* qbp = (const ulonglong2*)qb_s;
#pragma unroll
            for (int j = 0; j < 16; j++) { ulonglong2 v = qbp[j]; fma2(a0, rr[2*j], v.x); fma2(a1, rr[2*j+1], v.y); }
            float2 f0 = upk2(a0), f1 = upk2(a1);
            g_kb2[b * 256 + m] = QSCALE * (f0.x + f0.y + f1.x + f1.y);
        }
        int ch = m >> 6, nt = (m & 63) >> 3, g = m & 7;
        int i0 = (part - 4) * 16;
        __nv_bfloat16* dst = (__nv_bfloat16*)g_K2p + b * 16384;
        for (int ii = 0; ii < 16; ii++) {
            int i = i0 + ii;
            u64 a0 = pk2(0.f, 0.f), a1 = pk2(0.f, 0.f);
            const ulonglong2* qp = (const ulonglong2*)&wmat[i * 68];
#pragma unroll
            for (int j = 0; j < 16; j++) { ulonglong2 v = qp[j]; fma2(a0, rr[2*j], v.x); fma2(a1, rr[2*j+1], v.y); }
            float2 f0 = upk2(a0), f1 = upk2(a1);
            float val = QSCALE * (f0.x + f0.y + f1.x + f1.y);
            int ks = i >> 4, r = i & 15, h = r >> 3, r7 = r & 7, tig = r7 >> 1, j = r7 & 1;
            dst[(((ch * 4 + ks) * 32 + g * 4 + tig) * 16 + nt * 2 + h) * 2 + j] =
                __float2bfloat16(val);
        }
    } else {
        int ch = m >> 6, r = m & 63, ks = r >> 4, r15 = r & 15, h = r15 >> 3,
            q = r15 & 7, tig = q >> 1, j = q & 1;
        int c0 = part * 16;
        __nv_bfloat16* dst = (__nv_bfloat16*)g_V2p + b * 16384;
        for (int cc = 0; cc < 16; cc++) {
            int c = c0 + cc;
            u64 a0 = pk2(0.f, 0.f), a1 = pk2(0.f, 0.f);
            const ulonglong2* pp = (const ulonglong2*)&wmat[c * 68];
#pragma unroll
            for (int jj = 0; jj < 16; jj++) { ulonglong2 v = pp[jj]; fma2(a0, rr[2*jj], v.x); fma2(a1, rr[2*jj+1], v.y); }
            float2 f0 = upk2(a0), f1 = upk2(a1);
            float val = f0.x + f0.y + f1.x + f1.y;
            int nt = c >> 3, g = c & 7;
            dst[(((ch * 4 + ks) * 32 + g * 4 + tig) * 16 + nt * 2 + h) * 2 + j] =
                __float2bfloat16(val);
            red[cc * 257 + m] = val;
        }
        __syncthreads();
        int cl = tid >> 4, seg = tid & 15;
        float s = 0.f;
#pragma unroll
        for (int jj = 0; jj < 16; jj++) s += red[cl * 257 + seg * 16 + jj];
#pragma unroll
        for (int o = 8; o; o >>= 1) s += __shfl_down_sync(0xffffffffu, s, o, 16);
        if (seg == 0) g_colsum[b * 64 + c0 + cl] = s;
    }
}

// ============================================================
// Kernel 3: bf16 m16n8k16 attention. 256 threads (8 warps), 2 CTAs/SM.
// Warp owns 16 query rows; Xs(bf16) overlays P(bf16) per warp.
// ============================================================
namespace {
constexpr int TPC   = 4;
// float-unit offsets
constexpr int F_K2  = 0;                       // 512 entries x 5 float4 = 10240 f
constexpr int F_V2  = 10240;                   // 10240 f
constexpr int F_XS  = 20480;                   // Xs/P: 128 rows x 36 u32 = 4608
constexpr int F_KB  = 25088;                   // kb2[256]
constexpr int F_CS  = 25344;                   // colsum[64]
constexpr int F_PB  = 25408;                   // pb[64]
constexpr int ATTN_FLOATS = 25472;
constexpr int ATTN_BYTES  = ATTN_FLOATS * 4;   // 101888
}

__global__ void __launch_bounds__(256, 2) k_attn6(
    const float* __restrict__ x, const float* __restrict__ pb,
    float* __restrict__ out)
{
    extern __shared__ float sm[];
    u32* smu = (u32*)sm;
    int tid  = threadIdx.x;
    int w    = tid >> 5, lane = tid & 31;
    int g    = lane >> 2, tig = lane & 3;
    int b    = blockIdx.y;

    // ---- per-batch staging: bf16 packs into pitch-5-float4 lanes ----
    {
        float4* k2d = (float4*)(sm + F_K2);
        float4* v2d = (float4*)(sm + F_V2);
        const float4* k2s = (const float4*)g_K2p + b * 2048;
        const float4* v2s = (const float4*)g_V2p + b * 2048;
#pragma unroll
        for (int j = 0; j < 8; j++) {
            int idx4 = tid + j * 256;
            int entry = idx4 >> 2, jj = idx4 & 3;
            k2d[entry * 5 + jj] = k2s[idx4];
            v2d[entry * 5 + jj] = v2s[idx4];
        }
    }
    sm[F_KB + tid] = g_kb2[b * 256 + tid];
    if (tid < 64) {
        sm[F_CS + tid] = g_colsum[b * 64 + tid];
        sm[F_PB + tid] = pb[tid];
    }

    const float* kb2s = sm + F_KB;
    u32* Pw = smu + F_XS + w * 16 * 36;       // overlays this warp's Xs rows

    for (int t = 0; t < TPC; t++) {
        int q0 = (blockIdx.x * TPC + t) * 128;
        __syncthreads();                       // prior-tile P / staging done
        // ---- stage x tile as bf16, pitch 36 u32 ----
#pragma unroll
        for (int j = 0; j < 8; j++) {
            int idx4 = tid + j * 256;          // 2048 float4 = 128 x 16
            int row = idx4 >> 4, c4 = idx4 & 15;
            float4 v = ((const float4*)x)[(size_t)(b * NN + q0 + row) * 16 + c4];
            u32 lo = bfx2(v.x, v.y), hi = bfx2(v.z, v.w);
            u64 pair = (u64)lo | ((u64)hi << 32);
            *(u64*)&smu[F_XS + row * 36 + c4 * 2] = pair;
        }
        __syncthreads();

        // ---- hoist A fragments (own rows; Xs region then becomes P) ----
        u32 ah0[4], ah1[4], ah2[4], ah3[4];
        {
            const u32* xr0 = smu + F_XS + (16 * w + g) * 36;
            const u32* xr1 = xr0 + 8 * 36;
#pragma unroll
            for (int ks = 0; ks < 4; ks++) {
                ah0[ks] = xr0[ks * 8 + tig];
                ah1[ks] = xr1[ks * 8 + tig];
                ah2[ks] = xr0[ks * 8 + tig + 4];
                ah3[ks] = xr1[ks * 8 + tig + 4];
            }
        }
        __syncwarp();

        float of[8][4];
#pragma unroll
        for (int nt = 0; nt < 8; nt++)
#pragma unroll
            for (int i = 0; i < 4; i++) of[nt][i] = 0.f;
        float rs0 = 0.f, rs1 = 0.f;

#pragma unroll
        for (int ch = 0; ch < 4; ch++) {
            // ---- QK chunk: S[16 x 64] ----
            float sf[8][4];
#pragma unroll
            for (int nt = 0; nt < 8; nt++)
#pragma unroll
                for (int i = 0; i < 4; i++) sf[nt][i] = 0.f;
#pragma unroll
            for (int ks = 0; ks < 4; ks++) {
                const float4* bp = (const float4*)(sm + F_K2) + ((ch * 4 + ks) * 32 + lane) * 5;
                float4 B0 = bp[0], B1 = bp[1], B2 = bp[2], B3 = bp[3];
                u32 a0 = ah0[ks], a1 = ah1[ks], a2 = ah2[ks], a3 = ah3[ks];
                mmabf(sf[0], a0, a1, a2, a3, __float_as_uint(B0.x), __float_as_uint(B0.y));
                mmabf(sf[1], a0, a1, a2, a3, __float_as_uint(B0.z), __float_as_uint(B0.w));
                mmabf(sf[2], a0, a1, a2, a3, __float_as_uint(B1.x), __float_as_uint(B1.y));
                mmabf(sf[3], a0, a1, a2, a3, __float_as_uint(B1.z), __float_as_uint(B1.w));
                mmabf(sf[4], a0, a1, a2, a3, __float_as_uint(B2.x), __float_as_uint(B2.y));
                mmabf(sf[5], a0, a1, a2, a3, __float_as_uint(B2.z), __float_as_uint(B2.w));
                mmabf(sf[6], a0, a1, a2, a3, __float_as_uint(B3.x), __float_as_uint(B3.y));
                mmabf(sf[7], a0, a1, a2, a3, __float_as_uint(B3.z), __float_as_uint(B3.w));
            }
            // ---- exp(S + kb2) - 1 -> P (bf16, warp-private) ----
            int m0 = ch * 64;
#pragma unroll
            for (int nt = 0; nt < 8; nt++) {
                int mc = m0 + nt * 8 + 2 * tig;
                float k0 = kb2s[mc], k1 = kb2s[mc + 1];
                float e0 = __expf(sf[nt][0] + k0) - 1.f;
                float e1 = __expf(sf[nt][1] + k1) - 1.f;
                float e2 = __expf(sf[nt][2] + k0) - 1.f;
                float e3 = __expf(sf[nt][3] + k1) - 1.f;
                rs0 += e0 + e1;
                rs1 += e2 + e3;
                Pw[g * 36 + nt * 4 + tig]       = bfx2(e0, e1);
                Pw[(g + 8) * 36 + nt * 4 + tig] = bfx2(e2, e3);
            }
            __syncwarp();
            // ---- PV chunk: O += P[16 x 64] @ V2[64 x 64] ----
#pragma unroll
            for (int ks = 0; ks < 4; ks++) {
                u32 a0 = Pw[g * 36 + ks * 8 + tig];
                u32 a1 = Pw[(g + 8) * 36 + ks * 8 + tig];
                u32 a2 = Pw[g * 36 + ks * 8 + tig + 4];
                u32 a3 = Pw[(g + 8) * 36 + ks * 8 + tig + 4];
                const float4* vp = (const float4*)(sm + F_V2) + ((ch * 4 + ks) * 32 + lane) * 5;
                float4 C0 = vp[0], C1 = vp[1], C2 = vp[2], C3 = vp[3];
                mmabf(of[0], a0, a1, a2, a3, __float_as_uint(C0.x), __float_as_uint(C0.y));
                mmabf(of[1], a0, a1, a2, a3, __float_as_uint(C0.z), __float_as_uint(C0.w));
                mmabf(of[2], a0, a1, a2, a3, __float_as_uint(C1.x), __float_as_uint(C1.y));
                mmabf(of[3], a0, a1, a2, a3, __float_as_uint(C1.z), __float_as_uint(C1.w));
                mmabf(of[4], a0, a1, a2, a3, __float_as_uint(C2.x), __float_as_uint(C2.y));
                mmabf(of[5], a0, a1, a2, a3, __float_as_uint(C2.z), __float_as_uint(C2.w));
                mmabf(of[6], a0, a1, a2, a3, __float_as_uint(C3.x), __float_as_uint(C3.y));
                mmabf(of[7], a0, a1, a2, a3, __float_as_uint(C3.z), __float_as_uint(C3.w));
            }
            __syncwarp();                      // P reused next chunk
        }

        // ---- normalize + epilogue ----
        rs0 += __shfl_xor_sync(0xffffffffu, rs0, 1);
        rs0 += __shfl_xor_sync(0xffffffffu, rs0, 2);
        rs1 += __shfl_xor_sync(0xffffffffu, rs1, 1);
        rs1 += __shfl_xor_sync(0xffffffffu, rs1, 2);
        float inv0 = 1.f / (256.f + rs0);
        float inv1 = 1.f / (256.f + rs1);

        int qa  = q0 + 16 * w + g;
        int qb_ = qa + 8;
#pragma unroll
        for (int nt = 0; nt < 8; nt++) {
            int c = nt * 8 + 2 * tig;
            float cs0 = sm[F_CS + c], cs1 = sm[F_CS + c + 1];
            float pb0 = sm[F_PB + c], pb1 = sm[F_PB + c + 1];
            *(float2*)&out[(size_t)(b * NN + qa) * 64 + c] =
                make_float2((cs0 + of[nt][0]) * inv0 + pb0,
                            (cs1 + of[nt][1]) * inv0 + pb1);
            *(float2*)&out[(size_t)(b * NN + qb_) * 64 + c] =
                make_float2((cs0 + of[nt][2]) * inv1 + pb0,
                            (cs1 + of[nt][3]) * inv1 + pb1);
        }
    }
}

// ============================================================
extern "C" void kernel_launch(void* const* d_in, const int* in_sizes, int n_in,
                              void* d_out, int out_size) {
    const float* x   = (const float*)d_in[0];
    const float* srw = (const float*)d_in[1];
    const float* srb = (const float*)d_in[2];
    const float* lng = (const float*)d_in[3];
    const float* lnb = (const float*)d_in[4];
    const float* qw  = (const float*)d_in[5];
    const float* qb  = (const float*)d_in[6];
    const float* kvw = (const float*)d_in[7];
    const float* kvb = (const float*)d_in[8];
    const float* pw  = (const float*)d_in[9];
    const float* pb  = (const float*)d_in[10];
    float* out = (float*)d_out;

    k_wtrans<<<1024, 256>>>(srw);
    k_conv<<<dim3(32, 8), 256>>>(x);
    k_lnkv<<<32, 256>>>(srb, lng, lnb, kvw, kvb);
    k_fold<<<dim3(8, 8), 256>>>(qw, qb, pw);
    cudaFuncSetAttribute(k_attn6, cudaFuncAttributeMaxDynamicSharedMemorySize, ATTN_BYTES);
    k_attn6<<<dim3(NN / (128 * TPC), NB), 256, ATTN_BYTES>>>(x, pb, out);
}

// round 8
// speedup vs baseline: 8.6096x; 1.0408x over previous
#include <cuda_runtime.h>
#include <cuda_bf16.h>
#include <cstdint>
#include <cstddef>

// EfficientSelfAttention: B=8, N=16384 (128x128), C=64, heads=1, SR=8 -> Nr=256
// R7: register-resident P — the S C-fragment layout IS the PV A-fragment layout,
// so exp(S+kb)-1 packs straight into PV operands. No P smem, no intra-chunk sync.

namespace {
constexpr int   NB     = 8;
constexpr int   NN     = 16384;
constexpr float QSCALE = 0.125f;   // 64^-0.5
}

// ---- scratch ----
__device__ float g_wT[64 * 64 * 64];      // [k][oc]
__device__ float g_part[8 * 2048 * 64];   // conv split-k partials
__device__ float g_K[8 * 256 * 64];
__device__ float g_V[8 * 256 * 64];
__device__ unsigned int g_K2p[8 * 8192];  // bf16 QK B-frag pack
__device__ unsigned int g_V2p[8 * 8192];  // bf16 PV B-frag pack
__device__ float g_kb2[8 * 256];
__device__ float g_colsum[8 * 64];

using u64 = unsigned long long;
using u32 = unsigned int;

__device__ __forceinline__ u64 pk2(float x, float y) {
    u64 r; asm("mov.b64 %0,{%1,%2};" : "=l"(r) : "f"(x), "f"(y)); return r;
}
__device__ __forceinline__ float2 upk2(u64 v) {
    float2 f; asm("mov.b64 {%0,%1},%2;" : "=f"(f.x), "=f"(f.y) : "l"(v)); return f;
}
__device__ __forceinline__ void fma2(u64 &d, u64 a, u64 b) {
    asm("fma.rn.f32x2 %0,%1,%2,%0;" : "+l"(d) : "l"(a), "l"(b));
}
__device__ __forceinline__ u32 bfx2(float lo, float hi) {
    u32 r; asm("cvt.rn.bf16x2.f32 %0, %1, %2;" : "=r"(r) : "f"(hi), "f"(lo)); return r;
}
__device__ __forceinline__ void mmabf(float* d, u32 a0, u32 a1, u32 a2, u32 a3,
                                      u32 b0, u32 b1) {
    asm volatile(
        "mma.sync.aligned.m16n8k16.row.col.f32.bf16.bf16.f32 "
        "{%0,%1,%2,%3}, {%4,%5,%6,%7}, {%8,%9}, {%0,%1,%2,%3};"
        : "+f"(d[0]), "+f"(d[1]), "+f"(d[2]), "+f"(d[3])
        : "r"(a0), "r"(a1), "r"(a2), "r"(a3), "r"(b0), "r"(b1));
}

// ============================================================
// Kernel 1a: transpose sr_w -> wT[k][oc]
// ============================================================
__global__ void k_wtrans(const float* __restrict__ srw) {
    int d   = blockIdx.x * 256 + threadIdx.x;
    int oc  = d & 63;
    int k   = d >> 6;
    int ic  = k & 63;
    int pix = k >> 6;
    g_wT[d] = srw[(oc << 12) + (ic << 6) + pix];
}

// ============================================================
// Kernel 1b: conv v2 (unchanged — known good)
// ============================================================
__global__ void __launch_bounds__(256) k_conv(const float* __restrict__ x) {
    __shared__ float A_sT[64 * 68];
    __shared__ float W_s[64 * 68];
    int tid = threadIdx.x;
    int pt = blockIdx.x, kt = blockIdx.y;
    int to = tid & 15, tp = tid >> 4;

    u64 acc[4][2];
#pragma unroll
    for (int r = 0; r < 4; r++) { acc[r][0] = pk2(0.f, 0.f); acc[r][1] = pk2(0.f, 0.f); }

    for (int ck = 0; ck < 8; ck++) {
        int pix = kt * 8 + ck;
        int kb  = pix * 64;
#pragma unroll
        for (int j = 0; j < 4; j++) {
            int lin = tid + j * 256;
            int row = lin >> 4, c4 = lin & 15;
            *(float4*)&W_s[row * 68 + c4 * 4] = ((const float4*)(g_wT + kb * 64))[lin];
        }
#pragma unroll
        for (int j = 0; j < 4; j++) {
            int lin = tid + j * 256;
            int c4 = lin & 15, i = lin >> 4;
            int pos = pt * 64 + i;
            int b = pos >> 8, pp = pos & 255;
            int oh = pp >> 4, ow = pp & 15;
            int row = oh * 8 + (pix >> 3);
            int col = ow * 8 + (pix & 7);
            float4 v = ((const float4*)x)[(size_t)(b * 16384 + row * 128 + col) * 16 + c4];
            A_sT[(c4 * 4 + 0) * 68 + i] = v.x;
            A_sT[(c4 * 4 + 1) * 68 + i] = v.y;
            A_sT[(c4 * 4 + 2) * 68 + i] = v.z;
            A_sT[(c4 * 4 + 3) * 68 + i] = v.w;
        }
        __syncthreads();
#pragma unroll 4
        for (int kk = 0; kk < 64; kk++) {
            float4 av = *(const float4*)&A_sT[kk * 68 + tp * 4];
            ulonglong2 wv = *(const ulonglong2*)&W_s[kk * 68 + to * 4];
            u64 a0 = pk2(av.x, av.x), a1 = pk2(av.y, av.y);
            u64 a2 = pk2(av.z, av.z), a3 = pk2(av.w, av.w);
            fma2(acc[0][0], a0, wv.x); fma2(acc[0][1], a0, wv.y);
            fma2(acc[1][0], a1, wv.x); fma2(acc[1][1], a1, wv.y);
            fma2(acc[2][0], a2, wv.x); fma2(acc[2][1], a2, wv.y);
            fma2(acc[3][0], a3, wv.x); fma2(acc[3][1], a3, wv.y);
        }
        __syncthreads();
    }
    int pos0 = pt * 64 + tp * 4;
#pragma unroll
    for (int r = 0; r < 4; r++) {
        float2 f0 = upk2(acc[r][0]), f1 = upk2(acc[r][1]);
        ((float4*)g_part)[(kt * 2048 + pos0 + r) * 16 + to] =
            make_float4(f0.x, f0.y, f1.x, f1.y);
    }
}

// ============================================================
// Kernel 2: sum 8 partials + bias -> LayerNorm -> KV projection (unchanged)
// ============================================================
__global__ void __launch_bounds__(256) k_lnkv(
    const float* __restrict__ srb, const float* __restrict__ lng,
    const float* __restrict__ lnb, const float* __restrict__ kvw,
    const float* __restrict__ kvb)
{
    __shared__ float kvw_s[128 * 68];
    __shared__ float xn_s[8 * 68];
    __shared__ float kvb_s[128], srb_s[64], lg_s[64], lb_s[64];
    int tid = threadIdx.x;
#pragma unroll
    for (int j = 0; j < 8; j++) {
        int idx4 = tid + j * 256;
        int r = idx4 >> 4, c4 = idx4 & 15;
        ((float4*)kvw_s)[r * 17 + c4] = ((const float4*)kvw)[idx4];
    }
    if (tid < 128) kvb_s[tid] = kvb[tid];
    if (tid >= 128 && tid < 192) {
        int c = tid - 128;
        srb_s[c] = srb[c]; lg_s[c] = lng[c]; lb_s[c] = lnb[c];
    }
    __syncthreads();

    int w = tid >> 5, lane = tid & 31;
    for (int t = 0; t < 8; t++) {
        int row = blockIdx.x * 64 + w * 8 + t;
        int c0 = lane, c1 = lane + 32;
        float v0 = srb_s[c0], v1 = srb_s[c1];
#pragma unroll
        for (int kt = 0; kt < 8; kt++) {
            v0 += g_part[kt * 131072 + row * 64 + c0];
            v1 += g_part[kt * 131072 + row * 64 + c1];
        }
        float s = v0 + v1, sq = v0 * v0 + v1 * v1;
#pragma unroll
        for (int o = 16; o; o >>= 1) {
            s  += __shfl_xor_sync(0xffffffffu, s, o);
            sq += __shfl_xor_sync(0xffffffffu, sq, o);
        }
        float mu  = s * (1.f / 64.f);
        float var = sq * (1.f / 64.f) - mu * mu;
        float inv = rsqrtf(var + 1e-5f);
        xn_s[w * 68 + c0] = (v0 - mu) * inv * lg_s[c0] + lb_s[c0];
        xn_s[w * 68 + c1] = (v1 - mu) * inv * lg_s[c1] + lb_s[c1];
        __syncwarp();
#pragma unroll
        for (int rr = 0; rr < 4; rr++) {
            int r = lane + rr * 32;
            u64 acc0 = pk2(0.f, 0.f), acc1 = pk2(0.f, 0.f);
#pragma unroll
            for (int c4 = 0; c4 < 8; c4++) {
                ulonglong2 wv0 = *(const ulonglong2*)&kvw_s[r * 68 + c4 * 8];
                ulonglong2 xv0 = *(const ulonglong2*)&xn_s[w * 68 + c4 * 8];
                ulonglong2 wv1 = *(const ulonglong2*)&kvw_s[r * 68 + c4 * 8 + 4];
                ulonglong2 xv1 = *(const ulonglong2*)&xn_s[w * 68 + c4 * 8 + 4];
                fma2(acc0, wv0.x, xv0.x); fma2(acc1, wv0.y, xv0.y);
                fma2(acc0, wv1.x, xv1.x); fma2(acc1, wv1.y, xv1.y);
            }
            float2 f0 = upk2(acc0), f1 = upk2(acc1);
            float val = f0.x + f0.y + f1.x + f1.y + kvb_s[r];
            if (r < 64) g_K[row * 64 + r] = val;
            else        g_V[row * 64 + (r - 64)] = val;
        }
        __syncwarp();
    }
}

// ============================================================
// Kernel 2b: fold projections -> bf16 fragment packs.
// grid (8 batch, 16 part), 256 threads (thread = key m).
//  parts 0-7: V pack, 8 cols each + colsum;  parts 8-15: K pack, 8 i's (+kb2 on 8)
// ============================================================
__global__ void __launch_bounds__(256) k_fold(
    const float* __restrict__ qw, const float* __restrict__ qb,
    const float* __restrict__ pw)
{
    __shared__ float wmat[64 * 68];
    __shared__ float red[8 * 257];
    __shared__ float qb_s[64];
    int tid = threadIdx.x;
    int b = blockIdx.x, part = blockIdx.y;
    bool vpath = (part < 8);

#pragma unroll
    for (int j = 0; j < 4; j++) {
        int idx4 = tid + j * 256;
        int r = idx4 >> 4, c4 = idx4 & 15;
        if (vpath) {
            ((float4*)wmat)[r * 17 + c4] = ((const float4*)pw)[idx4];
        } else {
            float4 v = ((const float4*)qw)[idx4];
            wmat[(c4 * 4 + 0) * 68 + r] = v.x;
            wmat[(c4 * 4 + 1) * 68 + r] = v.y;
            wmat[(c4 * 4 + 2) * 68 + r] = v.z;
            wmat[(c4 * 4 + 3) * 68 + r] = v.w;
        }
    }
    if (tid < 64) qb_s[tid] = qb[tid];
    __syncthreads();

    int m = tid;
    u64 rr[32];
    {
        const float* src = vpath ? (g_V + (b * 256 + m) * 64) : (g_K + (b * 256 + m) * 64);
        const ulonglong2* s2 = (const ulonglong2*)src;
#pragma unroll
        for (int j = 0; j < 16; j++) { ulonglong2 v = s2[j]; rr[2*j] = v.x; rr[2*j+1] = v.y; }
    }

    if (!vpath) {
        if (part == 8) {
            u64 a0 = pk2(0.f, 0.f), a1 = pk2(0.f, 0.f);
            const ulonglong2* qbp = (const ulonglong2*)qb_s;
#pragma unroll
            for (int j = 0; j < 16; j++) { ulonglong2 v = qbp[j]; fma2(a0, rr[2*j], v.x); fma2(a1, rr[2*j+1], v.y); }
            float2 f0 = upk2(a0), f1 = upk2(a1);
            g_kb2[b * 256 + m] = QSCALE * (f0.x + f0.y + f1.x + f1.y);
        }
        int ch = m >> 6, nt = (m & 63) >> 3, g = m & 7;
        int i0 = (part - 8) * 8;
        __nv_bfloat16* dst = (__nv_bfloat16*)g_K2p + b * 16384;
        for (int ii = 0; ii < 8; ii++) {
            int i = i0 + ii;
            u64 a0 = pk2(0.f, 0.f), a1 = pk2(0.f, 0.f);
            u64 a2 = pk2(0.f, 0.f), a3 = pk2(0.f, 0.f);
            const ulonglong2* qp = (const ulonglong2*)&wmat[i * 68];
#pragma unroll
            for (int j = 0; j < 8; j++) {
                ulonglong2 v0 = qp[2*j], v1 = qp[2*j+1];
                fma2(a0, rr[4*j],   v0.x); fma2(a1, rr[4*j+1], v0.y);
                fma2(a2, rr[4*j+2], v1.x); fma2(a3, rr[4*j+3], v1.y);
            }
            float2 f0 = upk2(a0), f1 = upk2(a1), f2 = upk2(a2), f3 = upk2(a3);
            float val = QSCALE * ((f0.x + f0.y) + (f1.x + f1.y) + (f2.x + f2.y) + (f3.x + f3.y));
            int ks = i >> 4, r = i & 15, h = r >> 3, r7 = r & 7, tig = r7 >> 1, j = r7 & 1;
            dst[(((ch * 4 + ks) * 32 + g * 4 + tig) * 16 + nt * 2 + h) * 2 + j] =
                __float2bfloat16(val);
        }
    } else {
        int ch = m >> 6, r = m & 63, ks = r >> 4, r15 = r & 15, h = r15 >> 3,
            q = r15 & 7, tig = q >> 1, j = q & 1;
        int c0 = part * 8;
        __nv_bfloat16* dst = (__nv_bfloat16*)g_V2p + b * 16384;
        for (int cc = 0; cc < 8; cc++) {
            int c = c0 + cc;
            u64 a0 = pk2(0.f, 0.f), a1 = pk2(0.f, 0.f);
            u64 a2 = pk2(0.f, 0.f), a3 = pk2(0.f, 0.f);
            const ulonglong2* pp = (const ulonglong2*)&wmat[c * 68];
#pragma unroll
            for (int jj = 0; jj < 8; jj++) {
                ulonglong2 v0 = pp[2*jj], v1 = pp[2*jj+1];
                fma2(a0, rr[4*jj],   v0.x); fma2(a1, rr[4*jj+1], v0.y);
                fma2(a2, rr[4*jj+2], v1.x); fma2(a3, rr[4*jj+3], v1.y);
            }
            float2 f0 = upk2(a0), f1 = upk2(a1), f2 = upk2(a2), f3 = upk2(a3);
            float val = (f0.x + f0.y) + (f1.x + f1.y) + (f2.x + f2.y) + (f3.x + f3.y);
            int nt = c >> 3, g = c & 7;
            dst[(((ch * 4 + ks) * 32 + g * 4 + tig) * 16 + nt * 2 + h) * 2 + j] =
                __float2bfloat16(val);
            red[cc * 257 + m] = val;
        }
        __syncthreads();
        // colsum: warp per column (8 cols)
        int cl = tid >> 5, seg = tid & 31;
        float s = 0.f;
#pragma unroll
        for (int jj = 0; jj < 8; jj++) s += red[cl * 257 + seg * 8 + jj];
#pragma unroll
        for (int o = 16; o; o >>= 1) s += __shfl_xor_sync(0xffffffffu, s, o);
        if (seg == 0) g_colsum[b * 64 + c0 + cl] = s;
    }
}

// ============================================================
// Kernel 3: bf16 attention, register-resident P. 256 threads, 2 CTAs/SM.
// ============================================================
namespace {
constexpr int TPC   = 4;
constexpr int F_K2  = 0;                       // 10240 f
constexpr int F_V2  = 10240;                   // 10240 f
constexpr int F_XS  = 20480;                   // Xs bf16: 128 x 36 u32
constexpr int F_KB  = 25088;
constexpr int F_CS  = 25344;
constexpr int F_PB  = 25408;
constexpr int ATTN_FLOATS = 25472;
constexpr int ATTN_BYTES  = ATTN_FLOATS * 4;   // 101888
}

__global__ void __launch_bounds__(256, 2) k_attn7(
    const float* __restrict__ x, const float* __restrict__ pb,
    float* __restrict__ out)
{
    extern __shared__ float sm[];
    u32* smu = (u32*)sm;
    int tid  = threadIdx.x;
    int w    = tid >> 5, lane = tid & 31;
    int g    = lane >> 2, tig = lane & 3;
    int b    = blockIdx.y;

    // ---- per-batch staging ----
    {
        float4* k2d = (float4*)(sm + F_K2);
        float4* v2d = (float4*)(sm + F_V2);
        const float4* k2s = (const float4*)g_K2p + b * 2048;
        const float4* v2s = (const float4*)g_V2p + b * 2048;
#pragma unroll
        for (int j = 0; j < 8; j++) {
            int idx4 = tid + j * 256;
            int entry = idx4 >> 2, jj = idx4 & 3;
            k2d[entry * 5 + jj] = k2s[idx4];
            v2d[entry * 5 + jj] = v2s[idx4];
        }
    }
    sm[F_KB + tid] = g_kb2[b * 256 + tid];
    if (tid < 64) {
        sm[F_CS + tid] = g_colsum[b * 64 + tid];
        sm[F_PB + tid] = pb[tid];
    }

    const float* kb2s = sm + F_KB;

    for (int t = 0; t < TPC; t++) {
        int q0 = (blockIdx.x * TPC + t) * 128;
        __syncthreads();
        // ---- stage x tile as bf16, pitch 36 u32 ----
#pragma unroll
        for (int j = 0; j < 8; j++) {
            int idx4 = tid + j * 256;
            int row = idx4 >> 4, c4 = idx4 & 15;
            float4 v = ((const float4*)x)[(size_t)(b * NN + q0 + row) * 16 + c4];
            u32 lo = bfx2(v.x, v.y), hi = bfx2(v.z, v.w);
            u64 pair = (u64)lo | ((u64)hi << 32);
            *(u64*)&smu[F_XS + row * 36 + c4 * 2] = pair;
        }
        __syncthreads();

        // ---- hoist A fragments ----
        u32 ah0[4], ah1[4], ah2[4], ah3[4];
        {
            const u32* xr0 = smu + F_XS + (16 * w + g) * 36;
            const u32* xr1 = xr0 + 8 * 36;
#pragma unroll
            for (int ks = 0; ks < 4; ks++) {
                ah0[ks] = xr0[ks * 8 + tig];
                ah1[ks] = xr1[ks * 8 + tig];
                ah2[ks] = xr0[ks * 8 + tig + 4];
                ah3[ks] = xr1[ks * 8 + tig + 4];
            }
        }

        float of[8][4];
#pragma unroll
        for (int nt = 0; nt < 8; nt++)
#pragma unroll
            for (int i = 0; i < 4; i++) of[nt][i] = 0.f;
        float rs0 = 0.f, rs1 = 0.f;

#pragma unroll
        for (int ch = 0; ch < 4; ch++) {
            // ---- QK chunk: S[16 x 64] ----
            float sf[8][4];
#pragma unroll
            for (int nt = 0; nt < 8; nt++)
#pragma unroll
                for (int i = 0; i < 4; i++) sf[nt][i] = 0.f;
#pragma unroll
            for (int ks = 0; ks < 4; ks++) {
                const float4* bp = (const float4*)(sm + F_K2) + ((ch * 4 + ks) * 32 + lane) * 5;
                float4 B0 = bp[0], B1 = bp[1], B2 = bp[2], B3 = bp[3];
                u32 a0 = ah0[ks], a1 = ah1[ks], a2 = ah2[ks], a3 = ah3[ks];
                mmabf(sf[0], a0, a1, a2, a3, __float_as_uint(B0.x), __float_as_uint(B0.y));
                mmabf(sf[1], a0, a1, a2, a3, __float_as_uint(B0.z), __float_as_uint(B0.w));
                mmabf(sf[2], a0, a1, a2, a3, __float_as_uint(B1.x), __float_as_uint(B1.y));
                mmabf(sf[3], a0, a1, a2, a3, __float_as_uint(B1.z), __float_as_uint(B1.w));
                mmabf(sf[4], a0, a1, a2, a3, __float_as_uint(B2.x), __float_as_uint(B2.y));
                mmabf(sf[5], a0, a1, a2, a3, __float_as_uint(B2.z), __float_as_uint(B2.w));
                mmabf(sf[6], a0, a1, a2, a3, __float_as_uint(B3.x), __float_as_uint(B3.y));
                mmabf(sf[7], a0, a1, a2, a3, __float_as_uint(B3.z), __float_as_uint(B3.w));
            }
            // ---- exp(S+kb)-1 -> register P (C-frag == A-frag layout) ----
            int m0 = ch * 64;
            u32 pe_lo[8], pe_hi[8];
#pragma unroll
            for (int nt = 0; nt < 8; nt++) {
                int mc = m0 + nt * 8 + 2 * tig;
                float k0 = kb2s[mc], k1 = kb2s[mc + 1];
                float e0 = __expf(sf[nt][0] + k0) - 1.f;
                float e1 = __expf(sf[nt][1] + k1) - 1.f;
                float e2 = __expf(sf[nt][2] + k0) - 1.f;
                float e3 = __expf(sf[nt][3] + k1) - 1.f;
                rs0 += e0 + e1;
                rs1 += e2 + e3;
                pe_lo[nt] = bfx2(e0, e1);
                pe_hi[nt] = bfx2(e2, e3);
            }
            // ---- PV chunk: O += P @ V2 (A direct from registers) ----
#pragma unroll
            for (int ks = 0; ks < 4; ks++) {
                u32 a0 = pe_lo[2 * ks],     a1 = pe_hi[2 * ks];
                u32 a2 = pe_lo[2 * ks + 1], a3 = pe_hi[2 * ks + 1];
                const float4* vp = (const float4*)(sm + F_V2) + ((ch * 4 + ks) * 32 + lane) * 5;
                float4 C0 = vp[0], C1 = vp[1], C2 = vp[2], C3 = vp[3];
                mmabf(of[0], a0, a1, a2, a3, __float_as_uint(C0.x), __float_as_uint(C0.y));
                mmabf(of[1], a0, a1, a2, a3, __float_as_uint(C0.z), __float_as_uint(C0.w));
                mmabf(of[2], a0, a1, a2, a3, __float_as_uint(C1.x), __float_as_uint(C1.y));
                mmabf(of[3], a0, a1, a2, a3, __float_as_uint(C1.z), __float_as_uint(C1.w));
                mmabf(of[4], a0, a1, a2, a3, __float_as_uint(C2.x), __float_as_uint(C2.y));
                mmabf(of[5], a0, a1, a2, a3, __float_as_uint(C2.z), __float_as_uint(C2.w));
                mmabf(of[6], a0, a1, a2, a3, __float_as_uint(C3.x), __float_as_uint(C3.y));
                mmabf(of[7], a0, a1, a2, a3, __float_as_uint(C3.z), __float_as_uint(C3.w));
            }
        }

        // ---- normalize + epilogue ----
        rs0 += __shfl_xor_sync(0xffffffffu, rs0, 1);
        rs0 += __shfl_xor_sync(0xffffffffu, rs0, 2);
        rs1 += __shfl_xor_sync(0xffffffffu, rs1, 1);
        rs1 += __shfl_xor_sync(0xffffffffu, rs1, 2);
        float inv0 = 1.f / (256.f + rs0);
        float inv1 = 1.f / (256.f + rs1);

        int qa  = q0 + 16 * w + g;
        int qb_ = qa + 8;
#pragma unroll
        for (int nt = 0; nt < 8; nt++) {
            int c = nt * 8 + 2 * tig;
            float cs0 = sm[F_CS + c], cs1 = sm[F_CS + c + 1];
            float pb0 = sm[F_PB + c], pb1 = sm[F_PB + c + 1];
            *(float2*)&out[(size_t)(b * NN + qa) * 64 + c] =
                make_float2((cs0 + of[nt][0]) * inv0 + pb0,
                            (cs1 + of[nt][1]) * inv0 + pb1);
            *(float2*)&out[(size_t)(b * NN + qb_) * 64 + c] =
                make_float2((cs0 + of[nt][2]) * inv1 + pb0,
                            (cs1 + of[nt][3]) * inv1 + pb1);
        }
    }
}

// ============================================================
extern "C" void kernel_launch(void* const* d_in, const int* in_sizes, int n_in,
                              void* d_out, int out_size) {
    const float* x   = (const float*)d_in[0];
    const float* srw = (const float*)d_in[1];
    const float* srb = (const float*)d_in[2];
    const float* lng = (const float*)d_in[3];
    const float* lnb = (const float*)d_in[4];
    const float* qw  = (const float*)d_in[5];
    const float* qb  = (const float*)d_in[6];
    const float* kvw = (const float*)d_in[7];
    const float* kvb = (const float*)d_in[8];
    const float* pw  = (const float*)d_in[9];
    const float* pb  = (const float*)d_in[10];
    float* out = (float*)d_out;

    k_wtrans<<<1024, 256>>>(srw);
    k_conv<<<dim3(32, 8), 256>>>(x);
    k_lnkv<<<32, 256>>>(srb, lng, lnb, kvw, kvb);
    k_fold<<<dim3(8, 16), 256>>>(qw, qb, pw);
    cudaFuncSetAttribute(k_attn7, cudaFuncAttributeMaxDynamicSharedMemorySize, ATTN_BYTES);
    k_attn7<<<dim3(NN / (128 * TPC), NB), 256, ATTN_BYTES>>>(x, pb, out);
}

// round 10
// speedup vs baseline: 12.9505x; 1.5042x over previous
#include <cuda_runtime.h>
#include <cuda_bf16.h>
#include <cstdint>
#include <cstddef>

// EfficientSelfAttention: B=8, N=16384 (128x128), C=64, heads=1, SR=8 -> Nr=256
// R8: conv on bf16 split-mma (3-product, ~2^-16 exact); lnkv+fold fused;
// attention grid balanced to exactly 2 CTAs/SM with flat tile ranges.

namespace {
constexpr int   NB     = 8;
constexpr int   NN     = 16384;
constexpr float QSCALE = 0.125f;   // 64^-0.5
}

// ---- scratch ----
__device__ float g_Wp[64 * 64 * 64];      // conv W bf16 hi/lo fragment pack (1MB as u32 via cast)
__device__ float g_part[8 * 2048 * 64];   // conv split-k partials
__device__ unsigned int g_K2p[8 * 8192];  // bf16 QK B-frag pack
__device__ unsigned int g_V2p[8 * 8192];  // bf16 PV B-frag pack
__device__ float g_kb2[8 * 256];
__device__ float g_colsum[8 * 64];

using u64 = unsigned long long;
using u32 = unsigned int;

__device__ __forceinline__ u64 pk2(float x, float y) {
    u64 r; asm("mov.b64 %0,{%1,%2};" : "=l"(r) : "f"(x), "f"(y)); return r;
}
__device__ __forceinline__ float2 upk2(u64 v) {
    float2 f; asm("mov.b64 {%0,%1},%2;" : "=f"(f.x), "=f"(f.y) : "l"(v)); return f;
}
__device__ __forceinline__ void fma2(u64 &d, u64 a, u64 b) {
    asm("fma.rn.f32x2 %0,%1,%2,%0;" : "+l"(d) : "l"(a), "l"(b));
}
__device__ __forceinline__ u32 bfx2(float lo, float hi) {
    u32 r; asm("cvt.rn.bf16x2.f32 %0, %1, %2;" : "=r"(r) : "f"(hi), "f"(lo)); return r;
}
__device__ __forceinline__ void mmabf(float* d, u32 a0, u32 a1, u32 a2, u32 a3,
                                      u32 b0, u32 b1) {
    asm volatile(
        "mma.sync.aligned.m16n8k16.row.col.f32.bf16.bf16.f32 "
        "{%0,%1,%2,%3}, {%4,%5,%6,%7}, {%8,%9}, {%0,%1,%2,%3};"
        : "+f"(d[0]), "+f"(d[1]), "+f"(d[2]), "+f"(d[3])
        : "r"(a0), "r"(a1), "r"(a2), "r"(a3), "r"(b0), "r"(b1));
}

// ============================================================
// Kernel 1: pack conv weights into bf16 hi/lo B-fragment order + zero colsum.
// g_Wp float4 layout: [chunk=pix(64)][s4(4)][wn(2)][lane(32)][f(4)]
//   f: 0=b0hi(nt0..3), 1=b1hi, 2=b0lo, 3=b1lo   (nt local to wn half)
// ============================================================
__global__ void __launch_bounds__(256) k_wpack(const float* __restrict__ srw) {
    int e = blockIdx.x * 256 + threadIdx.x;       // float4 index, 65536 total
    int zi = e;
    if (zi < 512) g_colsum[zi] = 0.f;

    int f    = e & 3;
    int tmp  = e >> 2;                            // entry
    int lane = tmp & 31;
    int wn   = (tmp >> 5) & 1;
    int s4   = (tmp >> 6) & 3;
    int pix  = tmp >> 8;                          // 0..63
    int g    = lane >> 2, tig = lane & 3;
    int ic0  = s4 * 16 + (f & 1) * 8 + tig * 2;
    bool lo  = (f >= 2);

    float4 out;
    float* op = (float*)&out;
#pragma unroll
    for (int ntl = 0; ntl < 4; ntl++) {
        int oc = (wn * 4 + ntl) * 8 + g;
        float w0 = srw[oc * 4096 + ic0 * 64 + pix];
        float w1 = srw[oc * 4096 + (ic0 + 1) * 64 + pix];
        u32 h = bfx2(w0, w1);
        u32 v;
        if (!lo) v = h;
        else {
            float h0 = __uint_as_float(h << 16);
            float h1 = __uint_as_float(h & 0xffff0000u);
            v = bfx2(w0 - h0, w1 - h1);
        }
        op[ntl] = __uint_as_float(v);
    }
    ((float4*)g_Wp)[e] = out;
}

// ============================================================
// Kernel 2: conv via bf16 split mma. CTA = 64 pos x 64 oc, k-split kt (512 k).
// grid (32, 8), 256 threads. Warp: wq=w&3 (16 pos), wn=w>>2 (32 oc).
// ============================================================
__global__ void __launch_bounds__(256) k_convm(const float* __restrict__ x) {
    __shared__ u32    A_s[64 * 72];      // [pos][pair*2 {hi,lo}], pad to 72
    __shared__ float4 W_s[256 * 5];      // entries (s4*2+wn)*32+lane, pitch 5
    int tid = threadIdx.x;
    int pt = blockIdx.x, kt = blockIdx.y;
    int w = tid >> 5, lane = tid & 31;
    int wq = w & 3, wn = w >> 2;
    int g = lane >> 2, tig = lane & 3;

    float acc[4][4];
#pragma unroll
    for (int nt = 0; nt < 4; nt++)
#pragma unroll
        for (int i = 0; i < 4; i++) acc[nt][i] = 0.f;

    for (int ck = 0; ck < 8; ck++) {
        int pix = kt * 8 + ck;
        // stage W chunk (1024 consecutive float4), pitch-5 scatter
        {
            const float4* wsrc = (const float4*)g_Wp + pix * 1024;
#pragma unroll
            for (int j = 0; j < 4; j++) {
                int idx4 = tid + j * 256;
                int e = idx4 >> 2, jj = idx4 & 3;
                W_s[e * 5 + jj] = wsrc[idx4];
            }
        }
        // stage x chunk: 64 pos x 64 ic -> bf16 hi/lo pairs
#pragma unroll
        for (int j = 0; j < 4; j++) {
            int lin = tid + j * 256;
            int c4 = lin & 15, i = lin >> 4;
            int pos = pt * 64 + i;
            int b = pos >> 8, pp = pos & 255;
            int oh = pp >> 4, ow = pp & 15;
            int row = oh * 8 + (pix >> 3);
            int col = ow * 8 + (pix & 7);
            float4 v = ((const float4*)x)[(size_t)(b * 16384 + row * 128 + col) * 16 + c4];
            u32 h01 = bfx2(v.x, v.y);
            u32 l01 = bfx2(v.x - __uint_as_float(h01 << 16),
                           v.y - __uint_as_float(h01 & 0xffff0000u));
            u32 h23 = bfx2(v.z, v.w);
            u32 l23 = bfx2(v.z - __uint_as_float(h23 << 16),
                           v.w - __uint_as_float(h23 & 0xffff0000u));
            *(uint4*)&A_s[i * 72 + c4 * 4] = make_uint4(h01, l01, h23, l23);
        }
        __syncthreads();

#pragma unroll
        for (int s4 = 0; s4 < 4; s4++) {
            int r0 = wq * 16 + g;
            int p0 = s4 * 8 + tig;
            u64 A0 = *(const u64*)&A_s[r0 * 72 + p0 * 2];
            u64 A1 = *(const u64*)&A_s[(r0 + 8) * 72 + p0 * 2];
            u64 A2 = *(const u64*)&A_s[r0 * 72 + (p0 + 4) * 2];
            u64 A3 = *(const u64*)&A_s[(r0 + 8) * 72 + (p0 + 4) * 2];
            u32 a0h = (u32)A0, a0l = (u32)(A0 >> 32);
            u32 a1h = (u32)A1, a1l = (u32)(A1 >> 32);
            u32 a2h = (u32)A2, a2l = (u32)(A2 >> 32);
            u32 a3h = (u32)A3, a3l = (u32)(A3 >> 32);

            const float4* wp = &W_s[((s4 * 2 + wn) * 32 + lane) * 5];
            float4 B0h = wp[0], B1h = wp[1], B0l = wp[2], B1l = wp[3];
            const float* b0h = (const float*)&B0h;
            const float* b1h = (const float*)&B1h;
            const float* b0l = (const float*)&B0l;
            const float* b1l = (const float*)&B1l;
#pragma unroll
            for (int nt = 0; nt < 4; nt++) {
                u32 bh0 = __float_as_uint(b0h[nt]), bh1 = __float_as_uint(b1h[nt]);
                u32 bl0 = __float_as_uint(b0l[nt]), bl1 = __float_as_uint(b1l[nt]);
                mmabf(acc[nt], a0h, a1h, a2h, a3h, bh0, bh1);
                mmabf(acc[nt], a0h, a1h, a2h, a3h, bl0, bl1);
                mmabf(acc[nt], a0l, a1l, a2l, a3l, bh0, bh1);
            }
        }
        __syncthreads();
    }

    int pos0 = pt * 64 + wq * 16 + g;
#pragma unroll
    for (int nt = 0; nt < 4; nt++) {
        int oc = wn * 32 + nt * 8 + tig * 2;
        *(float2*)&g_part[kt * 131072 + pos0 * 64 + oc] = make_float2(acc[nt][0], acc[nt][1]);
        *(float2*)&g_part[kt * 131072 + (pos0 + 8) * 64 + oc] = make_float2(acc[nt][2], acc[nt][3]);
    }
}

// ============================================================
// Kernel 3: fused partial-sum + bias + LayerNorm + KV proj + fold packs.
// grid 128 (16 rows each), 256 threads; warp handles 2 rows.
// ============================================================
namespace {
constexpr int L_KVW = 0;                 // 128*68
constexpr int L_QWT = 8704;              // 64*68
constexpr int L_PW  = 13056;             // 64*68
constexpr int L_XN  = 17408;             // 8*68
constexpr int L_KR  = 17952;             // 8*68
constexpr int L_VR  = 18496;             // 8*68
constexpr int L_QB  = 19040;
constexpr int L_SRB = 19104;
constexpr int L_LG  = 19168;
constexpr int L_LB  = 19232;
constexpr int L_CAC = 19296;             // 64
constexpr int L_KVB = 19360;             // 128
constexpr int LNF_FLOATS = 19488;
constexpr int LNF_BYTES  = LNF_FLOATS * 4;   // 77952
}

__global__ void __launch_bounds__(256) k_lnf(
    const float* __restrict__ srb, const float* __restrict__ lng,
    const float* __restrict__ lnb, const float* __restrict__ kvw,
    const float* __restrict__ kvb, const float* __restrict__ qw,
    const float* __restrict__ qb,  const float* __restrict__ pw)
{
    extern __shared__ float sm[];
    int tid = threadIdx.x;
    int w = tid >> 5, lane = tid & 31;

    // ---- stage weights ----
#pragma unroll
    for (int j = 0; j < 8; j++) {                 // kvw 2048 f4
        int idx4 = tid + j * 256;
        int r = idx4 >> 4, c4 = idx4 & 15;
        ((float4*)(sm + L_KVW))[r * 17 + c4] = ((const float4*)kvw)[idx4];
    }
#pragma unroll
    for (int j = 0; j < 4; j++) {                 // qw -> qwT, pw
        int idx4 = tid + j * 256;
        int r = idx4 >> 4, c4 = idx4 & 15;
        float4 v = ((const float4*)qw)[idx4];
        sm[L_QWT + (c4 * 4 + 0) * 68 + r] = v.x;
        sm[L_QWT + (c4 * 4 + 1) * 68 + r] = v.y;
        sm[L_QWT + (c4 * 4 + 2) * 68 + r] = v.z;
        sm[L_QWT + (c4 * 4 + 3) * 68 + r] = v.w;
        ((float4*)(sm + L_PW))[r * 17 + c4] = ((const float4*)pw)[idx4];
    }
    if (tid < 64) {
        sm[L_QB  + tid] = qb[tid];
        sm[L_SRB + tid] = srb[tid];
        sm[L_LG  + tid] = lng[tid];
        sm[L_LB  + tid] = lnb[tid];
        sm[L_CAC + tid] = 0.f;
    }
    if (tid >= 64 && tid < 192) sm[L_KVB + tid - 64] = kvb[tid - 64];
    __syncthreads();

    int bb = blockIdx.x >> 4;   // batch (16 CTAs per batch)
    __nv_bfloat16* dK = (__nv_bfloat16*)g_K2p + bb * 16384;
    __nv_bfloat16* dV = (__nv_bfloat16*)g_V2p + bb * 16384;

    for (int t = 0; t < 2; t++) {
        int row = blockIdx.x * 16 + w * 2 + t;
        int m = row & 255;
        int c0 = lane, c1 = lane + 32;
        // ---- partial sum + conv bias ----
        float v0 = sm[L_SRB + c0], v1 = sm[L_SRB + c1];
#pragma unroll
        for (int kt = 0; kt < 8; kt++) {
            v0 += g_part[kt * 131072 + row * 64 + c0];
            v1 += g_part[kt * 131072 + row * 64 + c1];
        }
        // ---- LayerNorm ----
        float s = v0 + v1, sq = v0 * v0 + v1 * v1;
#pragma unroll
        for (int o = 16; o; o >>= 1) {
            s  += __shfl_xor_sync(0xffffffffu, s, o);
            sq += __shfl_xor_sync(0xffffffffu, sq, o);
        }
        float mu  = s * (1.f / 64.f);
        float var = sq * (1.f / 64.f) - mu * mu;
        float inv = rsqrtf(var + 1e-5f);
        sm[L_XN + w * 68 + c0] = (v0 - mu) * inv * sm[L_LG + c0] + sm[L_LB + c0];
        sm[L_XN + w * 68 + c1] = (v1 - mu) * inv * sm[L_LG + c1] + sm[L_LB + c1];
        __syncwarp();
        // ---- KV projection -> krow, vrow ----
#pragma unroll
        for (int rr = 0; rr < 4; rr++) {
            int r = lane + rr * 32;
            u64 a0 = pk2(0.f, 0.f), a1 = pk2(0.f, 0.f);
#pragma unroll
            for (int c4 = 0; c4 < 16; c4++) {
                ulonglong2 wv = *(const ulonglong2*)&sm[L_KVW + r * 68 + c4 * 4];
                ulonglong2 xv = *(const ulonglong2*)&sm[L_XN + w * 68 + c4 * 4];
                fma2(a0, wv.x, xv.x); fma2(a1, wv.y, xv.y);
            }
            float2 f0 = upk2(a0), f1 = upk2(a1);
            float val = f0.x + f0.y + f1.x + f1.y + sm[L_KVB + r];
            if (r < 64) sm[L_KR + w * 68 + r] = val;
            else        sm[L_VR + w * 68 + (r - 64)] = val;
        }
        __syncwarp();
        // ---- kb2 ----
        {
            float p = sm[L_QB + c0] * sm[L_KR + w * 68 + c0]
                    + sm[L_QB + c1] * sm[L_KR + w * 68 + c1];
#pragma unroll
            for (int o = 16; o; o >>= 1) p += __shfl_xor_sync(0xffffffffu, p, o);
            if (lane == 0) g_kb2[row] = QSCALE * p;
        }
        // ---- K2 pack (2 i's per lane) ----
        {
            int ch = m >> 6, nt = (m & 63) >> 3, gg = m & 7;
#pragma unroll
            for (int ii = 0; ii < 2; ii++) {
                int i = lane + ii * 32;
                u64 a0 = pk2(0.f, 0.f), a1 = pk2(0.f, 0.f);
#pragma unroll
                for (int c4 = 0; c4 < 16; c4++) {
                    ulonglong2 qv = *(const ulonglong2*)&sm[L_QWT + i * 68 + c4 * 4];
                    ulonglong2 kv = *(const ulonglong2*)&sm[L_KR + w * 68 + c4 * 4];
                    fma2(a0, qv.x, kv.x); fma2(a1, qv.y, kv.y);
                }
                float2 f0 = upk2(a0), f1 = upk2(a1);
                float val = QSCALE * (f0.x + f0.y + f1.x + f1.y);
                int ks = i >> 4, r = i & 15, h = r >> 3, r7 = r & 7, tg = r7 >> 1, jj = r7 & 1;
                dK[(((ch * 4 + ks) * 32 + gg * 4 + tg) * 16 + nt * 2 + h) * 2 + jj] =
                    __float2bfloat16(val);
            }
        }
        // ---- V2 pack + colsum (2 c's per lane) ----
        {
            int ch = m >> 6, r = m & 63, ks = r >> 4, r15 = r & 15, h = r15 >> 3,
                q = r15 & 7, tg = q >> 1, jj = q & 1;
#pragma unroll
            for (int cc = 0; cc < 2; cc++) {
                int c = lane + cc * 32;
                u64 a0 = pk2(0.f, 0.f), a1 = pk2(0.f, 0.f);
#pragma unroll
                for (int c4 = 0; c4 < 16; c4++) {
                    ulonglong2 pv = *(const ulonglong2*)&sm[L_PW + c * 68 + c4 * 4];
                    ulonglong2 vv = *(const ulonglong2*)&sm[L_VR + w * 68 + c4 * 4];
                    fma2(a0, pv.x, vv.x); fma2(a1, pv.y, vv.y);
                }
                float2 f0 = upk2(a0), f1 = upk2(a1);
                float val = f0.x + f0.y + f1.x + f1.y;
                int nt = c >> 3, gg = c & 7;
                dV[(((ch * 4 + ks) * 32 + gg * 4 + tg) * 16 + nt * 2 + h) * 2 + jj] =
                    __float2bfloat16(val);
                atomicAdd(&sm[L_CAC + c], val);
            }
        }
        __syncwarp();
    }
    __syncthreads();
    if (tid < 64) atomicAdd(&g_colsum[bb * 64 + tid], sm[L_CAC + tid]);
}

// ============================================================
// Kernel 4: bf16 attention, register-resident P, balanced flat tiles.
// grid 296 = 148 SMs x 2 CTAs; CTA processes contiguous tile range.
// ============================================================
namespace {
constexpr int NTILES = 1024;                   // (NN/128) * NB
constexpr int NCTA   = 296;
constexpr int F_K2  = 0;
constexpr int F_V2  = 10240;
constexpr int F_XS  = 20480;
constexpr int F_KB  = 25088;
constexpr int F_CS  = 25344;
constexpr int F_PB  = 25408;
constexpr int ATTN_FLOATS = 25472;
constexpr int ATTN_BYTES  = ATTN_FLOATS * 4;   // 101888
}

__global__ void __launch_bounds__(256, 2) k_attn8(
    const float* __restrict__ x, const float* __restrict__ pb,
    float* __restrict__ out)
{
    extern __shared__ float sm[];
    u32* smu = (u32*)sm;
    int tid  = threadIdx.x;
    int w    = tid >> 5, lane = tid & 31;
    int g    = lane >> 2, tig = lane & 3;

    int start = (blockIdx.x * NTILES) / NCTA;
    int end   = ((blockIdx.x + 1) * NTILES) / NCTA;

    if (tid < 64) sm[F_PB + tid] = pb[tid];
    int bcur = -1;

    for (int tt = start; tt < end; tt++) {
        int bb = tt >> 7;
        int q0 = (tt & 127) * 128;

        __syncthreads();                       // prior tile compute done
        if (bb != bcur) {
            bcur = bb;
            float4* k2d = (float4*)(sm + F_K2);
            float4* v2d = (float4*)(sm + F_V2);
            const float4* k2s = (const float4*)g_K2p + bb * 2048;
            const float4* v2s = (const float4*)g_V2p + bb * 2048;
#pragma unroll
            for (int j = 0; j < 8; j++) {
                int idx4 = tid + j * 256;
                int e = idx4 >> 2, jj = idx4 & 3;
                k2d[e * 5 + jj] = k2s[idx4];
                v2d[e * 5 + jj] = v2s[idx4];
            }
            sm[F_KB + tid] = g_kb2[bb * 256 + tid];
            if (tid < 64) sm[F_CS + tid] = g_colsum[bb * 64 + tid];
        }
        // ---- stage x tile as bf16, pitch 36 u32 ----
#pragma unroll
        for (int j = 0; j < 8; j++) {
            int idx4 = tid + j * 256;
            int row = idx4 >> 4, c4 = idx4 & 15;
            float4 v = ((const float4*)x)[(size_t)(bb * NN + q0 + row) * 16 + c4];
            u32 lo = bfx2(v.x, v.y), hi = bfx2(v.z, v.w);
            u64 pair = (u64)lo | ((u64)hi << 32);
            *(u64*)&smu[F_XS + row * 36 + c4 * 2] = pair;
        }
        __syncthreads();

        // ---- hoist A fragments ----
        u32 ah0[4], ah1[4], ah2[4], ah3[4];
        {
            const u32* xr0 = smu + F_XS + (16 * w + g) * 36;
            const u32* xr1 = xr0 + 8 * 36;
#pragma unroll
            for (int ks = 0; ks < 4; ks++) {
                ah0[ks] = xr0[ks * 8 + tig];
                ah1[ks] = xr1[ks * 8 + tig];
                ah2[ks] = xr0[ks * 8 + tig + 4];
                ah3[ks] = xr1[ks * 8 + tig + 4];
            }
        }

        float of[8][4];
#pragma unroll
        for (int nt = 0; nt < 8; nt++)
#pragma unroll
            for (int i = 0; i < 4; i++) of[nt][i] = 0.f;
        float rs0 = 0.f, rs1 = 0.f;
        const float* kb2s = sm + F_KB;

#pragma unroll
        for (int ch = 0; ch < 4; ch++) {
            float sf[8][4];
#pragma unroll
            for (int nt = 0; nt < 8; nt++)
#pragma unroll
                for (int i = 0; i < 4; i++) sf[nt][i] = 0.f;
#pragma unroll
            for (int ks = 0; ks < 4; ks++) {
                const float4* bp = (const float4*)(sm + F_K2) + ((ch * 4 + ks) * 32 + lane) * 5;
                float4 B0 = bp[0], B1 = bp[1], B2 = bp[2], B3 = bp[3];
                u32 a0 = ah0[ks], a1 = ah1[ks], a2 = ah2[ks], a3 = ah3[ks];
                mmabf(sf[0], a0, a1, a2, a3, __float_as_uint(B0.x), __float_as_uint(B0.y));
                mmabf(sf[1], a0, a1, a2, a3, __float_as_uint(B0.z), __float_as_uint(B0.w));
                mmabf(sf[2], a0, a1, a2, a3, __float_as_uint(B1.x), __float_as_uint(B1.y));
                mmabf(sf[3], a0, a1, a2, a3, __float_as_uint(B1.z), __float_as_uint(B1.w));
                mmabf(sf[4], a0, a1, a2, a3, __float_as_uint(B2.x), __float_as_uint(B2.y));
                mmabf(sf[5], a0, a1, a2, a3, __float_as_uint(B2.z), __float_as_uint(B2.w));
                mmabf(sf[6], a0, a1, a2, a3, __float_as_uint(B3.x), __float_as_uint(B3.y));
                mmabf(sf[7], a0, a1, a2, a3, __float_as_uint(B3.z), __float_as_uint(B3.w));
            }
            int m0 = ch * 64;
            u32 pe_lo[8], pe_hi[8];
#pragma unroll
            for (int nt = 0; nt < 8; nt++) {
                int mc = m0 + nt * 8 + 2 * tig;
                float k0 = kb2s[mc], k1 = kb2s[mc + 1];
                float e0 = __expf(sf[nt][0] + k0) - 1.f;
                float e1 = __expf(sf[nt][1] + k1) - 1.f;
                float e2 = __expf(sf[nt][2] + k0) - 1.f;
                float e3 = __expf(sf[nt][3] + k1) - 1.f;
                rs0 += e0 + e1;
                rs1 += e2 + e3;
                pe_lo[nt] = bfx2(e0, e1);
                pe_hi[nt] = bfx2(e2, e3);
            }
#pragma unroll
            for (int ks = 0; ks < 4; ks++) {
                u32 a0 = pe_lo[2 * ks],     a1 = pe_hi[2 * ks];
                u32 a2 = pe_lo[2 * ks + 1], a3 = pe_hi[2 * ks + 1];
                const float4* vp = (const float4*)(sm + F_V2) + ((ch * 4 + ks) * 32 + lane) * 5;
                float4 C0 = vp[0], C1 = vp[1], C2 = vp[2], C3 = vp[3];
                mmabf(of[0], a0, a1, a2, a3, __float_as_uint(C0.x), __float_as_uint(C0.y));
                mmabf(of[1], a0, a1, a2, a3, __float_as_uint(C0.z), __float_as_uint(C0.w));
                mmabf(of[2], a0, a1, a2, a3, __float_as_uint(C1.x), __float_as_uint(C1.y));
                mmabf(of[3], a0, a1, a2, a3, __float_as_uint(C1.z), __float_as_uint(C1.w));
                mmabf(of[4], a0, a1, a2, a3, __float_as_uint(C2.x), __float_as_uint(C2.y));
                mmabf(of[5], a0, a1, a2, a3, __float_as_uint(C2.z), __float_as_uint(C2.w));
                mmabf(of[6], a0, a1, a2, a3, __float_as_uint(C3.x), __float_as_uint(C3.y));
                mmabf(of[7], a0, a1, a2, a3, __float_as_uint(C3.z), __float_as_uint(C3.w));
            }
        }

        // ---- normalize + epilogue ----
        rs0 += __shfl_xor_sync(0xffffffffu, rs0, 1);
        rs0 += __shfl_xor_sync(0xffffffffu, rs0, 2);
        rs1 += __shfl_xor_sync(0xffffffffu, rs1, 1);
        rs1 += __shfl_xor_sync(0xffffffffu, rs1, 2);
        float inv0 = 1.f / (256.f + rs0);
        float inv1 = 1.f / (256.f + rs1);

        int qa  = q0 + 16 * w + g;
        int qb_ = qa + 8;
#pragma unroll
        for (int nt = 0; nt < 8; nt++) {
            int c = nt * 8 + 2 * tig;
            float cs0 = sm[F_CS + c], cs1 = sm[F_CS + c + 1];
            float pb0 = sm[F_PB + c], pb1 = sm[F_PB + c + 1];
            *(float2*)&out[(size_t)(bb * NN + qa) * 64 + c] =
                make_float2((cs0 + of[nt][0]) * inv0 + pb0,
                            (cs1 + of[nt][1]) * inv0 + pb1);
            *(float2*)&out[(size_t)(bb * NN + qb_) * 64 + c] =
                make_float2((cs0 + of[nt][2]) * inv1 + pb0,
                            (cs1 + of[nt][3]) * inv1 + pb1);
        }
    }
}

// ============================================================
extern "C" void kernel_launch(void* const* d_in, const int* in_sizes, int n_in,
                              void* d_out, int out_size) {
    const float* x   = (const float*)d_in[0];
    const float* srw = (const float*)d_in[1];
    const float* srb = (const float*)d_in[2];
    const float* lng = (const float*)d_in[3];
    const float* lnb = (const float*)d_in[4];
    const float* qw  = (const float*)d_in[5];
    const float* qb  = (const float*)d_in[6];
    const float* kvw = (const float*)d_in[7];
    const float* kvb = (const float*)d_in[8];
    const float* pw  = (const float*)d_in[9];
    const float* pb  = (const float*)d_in[10];
    float* out = (float*)d_out;

    k_wpack<<<256, 256>>>(srw);
    k_convm<<<dim3(32, 8), 256>>>(x);
    cudaFuncSetAttribute(k_lnf, cudaFuncAttributeMaxDynamicSharedMemorySize, LNF_BYTES);
    k_lnf<<<128, 256, LNF_BYTES>>>(srb, lng, lnb, kvw, kvb, qw, qb, pw);
    cudaFuncSetAttribute(k_attn8, cudaFuncAttributeMaxDynamicSharedMemorySize, ATTN_BYTES);
    k_attn8<<<NCTA, 256, ATTN_BYTES>>>(x, pb, out);
}